// round 5
// baseline (speedup 1.0000x reference)
#include <cuda_runtime.h>
#include <cuda_bf16.h>
#include <math.h>
#include <cstdint>

// ---------------------------------------------------------------------------
// Problem constants
// ---------------------------------------------------------------------------
#define BB   2
#define NN   2048
#define DD   2048
#define HH   16
#define HKV  4
#define HD   128
#define QKVW (HH * HD + 2 * HKV * HD)     // 3072
#define KOFF (HH * HD)                    // 2048
#define VOFF (HH * HD + HKV * HD)         // 2560
#define SCALE 0.08838834764831845f

#define BK 32                  // K-chunk (elements)
#define TSTR 80                // smem row stride bytes (64 data + 16 pad)
#define TILE_B (128 * TSTR)    // 10240 B per tile
#define STAGE_B (4 * TILE_B)   // 40960 B per stage (Ahi|Alo|Bhi|Blo)
#define SMEM_SZ (2 * STAGE_B)  // 81920 B
#define OFF_AHI 0
#define OFF_ALO (TILE_B)
#define OFF_BHI (2 * TILE_B)
#define OFF_BLO (3 * TILE_B)

// ---------------------------------------------------------------------------
// Device scratch (__device__ globals — allocation-free)
// ---------------------------------------------------------------------------
__device__ float g_QKV[(size_t)BB * NN * QKVW];                      // 48 MB fp32
__device__ float g_S  [(size_t)BB * HH * NN * NN];                   // 512 MB fp32

__device__ __align__(128) __nv_bfloat16 g_xh  [(size_t)BB * NN * DD];
__device__ __align__(128) __nv_bfloat16 g_xl  [(size_t)BB * NN * DD];
__device__ __align__(128) __nv_bfloat16 g_WTh [(size_t)QKVW * DD];
__device__ __align__(128) __nv_bfloat16 g_WTl [(size_t)QKVW * DD];
__device__ __align__(128) __nv_bfloat16 g_WoTh[(size_t)DD * DD];
__device__ __align__(128) __nv_bfloat16 g_WoTl[(size_t)DD * DD];
__device__ __align__(128) __nv_bfloat16 g_Qh  [(size_t)BB * NN * HH * HD];
__device__ __align__(128) __nv_bfloat16 g_Ql  [(size_t)BB * NN * HH * HD];
__device__ __align__(128) __nv_bfloat16 g_Kh  [(size_t)BB * NN * HKV * HD];
__device__ __align__(128) __nv_bfloat16 g_Kl  [(size_t)BB * NN * HKV * HD];
__device__ __align__(128) __nv_bfloat16 g_Ph  [(size_t)BB * HH * NN * NN];   // 268 MB
__device__ __align__(128) __nv_bfloat16 g_Pl  [(size_t)BB * HH * NN * NN];   // 268 MB
__device__ __align__(128) __nv_bfloat16 g_Vth [(size_t)BB * HKV * HD * NN];
__device__ __align__(128) __nv_bfloat16 g_Vtl [(size_t)BB * HKV * HD * NN];
__device__ __align__(128) __nv_bfloat16 g_ctxh[(size_t)BB * NN * HH * HD];
__device__ __align__(128) __nv_bfloat16 g_ctxl[(size_t)BB * NN * HH * HD];

// ---------------------------------------------------------------------------
// PTX helpers
// ---------------------------------------------------------------------------
__device__ __forceinline__ uint32_t smem_u32(const void* p) {
    uint32_t a;
    asm("{ .reg .u64 t; cvta.to.shared.u64 t, %1; cvt.u32.u64 %0, t; }" : "=r"(a) : "l"(p));
    return a;
}
__device__ __forceinline__ void ldmx4(uint32_t& r0, uint32_t& r1, uint32_t& r2, uint32_t& r3, uint32_t addr) {
    asm volatile("ldmatrix.sync.aligned.m8n8.x4.shared.b16 {%0,%1,%2,%3}, [%4];"
                 : "=r"(r0), "=r"(r1), "=r"(r2), "=r"(r3) : "r"(addr));
}
__device__ __forceinline__ void mma16816(float* c, const uint32_t* a, const uint32_t* b) {
    asm volatile(
        "mma.sync.aligned.m16n8k16.row.col.f32.bf16.bf16.f32 "
        "{%0,%1,%2,%3}, {%4,%5,%6,%7}, {%8,%9}, {%0,%1,%2,%3};"
        : "+f"(c[0]), "+f"(c[1]), "+f"(c[2]), "+f"(c[3])
        : "r"(a[0]), "r"(a[1]), "r"(a[2]), "r"(a[3]), "r"(b[0]), "r"(b[1]));
}
__device__ __forceinline__ void cpasync16(uint32_t dst, const void* src) {
    asm volatile("cp.async.cg.shared.global [%0], [%1], 16;" :: "r"(dst), "l"(src));
}
#define CP_COMMIT() asm volatile("cp.async.commit_group;" ::: "memory")
#define CP_WAIT(n)  asm volatile("cp.async.wait_group %0;" :: "n"(n) : "memory")

__device__ __forceinline__ void split1(float v, __nv_bfloat16& h, __nv_bfloat16& l) {
    h = __float2bfloat16(v);
    l = __float2bfloat16(v - __bfloat162float(h));
}
__device__ __forceinline__ uint32_t packbf2(__nv_bfloat16 a, __nv_bfloat16 b) {
    __nv_bfloat162 v = __halves2bfloat162(a, b);
    return *reinterpret_cast<uint32_t*>(&v);
}

// ---------------------------------------------------------------------------
// cp.async loader for one stage (all 4 tiles, 8 transfers / thread)
// ---------------------------------------------------------------------------
__device__ __forceinline__ void load_stage(
    uint32_t sbase,
    const __nv_bfloat16* __restrict__ Ah, const __nv_bfloat16* __restrict__ Al, int lda,
    const __nv_bfloat16* __restrict__ Bh, const __nv_bfloat16* __restrict__ Bl, int ldb,
    int k0, int r0, int c0)
{
    #pragma unroll
    for (int i = 0; i < 2; ++i) {
        int row = r0 + i * 64;
        uint32_t soff = (uint32_t)(row * TSTR + c0 * 16);
        size_t ga = (size_t)row * lda + k0 + c0 * 8;
        size_t gb = (size_t)row * ldb + k0 + c0 * 8;
        cpasync16(sbase + OFF_AHI + soff, Ah + ga);
        cpasync16(sbase + OFF_ALO + soff, Al + ga);
        cpasync16(sbase + OFF_BHI + soff, Bh + gb);
        cpasync16(sbase + OFF_BLO + soff, Bl + gb);
    }
}

// ---------------------------------------------------------------------------
// Mainloop: acc += A[128,K] @ B[128,K]^T  (bf16 hi/lo 3-MMA, fp32 acc)
// 256 threads; warps 4(M) x 2(N); warp tile 32x64; 2-stage cp.async pipeline.
// ---------------------------------------------------------------------------
__device__ __forceinline__ void mma_mainloop(
    const __nv_bfloat16* __restrict__ Ah, const __nv_bfloat16* __restrict__ Al, int lda,
    const __nv_bfloat16* __restrict__ Bh, const __nv_bfloat16* __restrict__ Bl, int ldb,
    int K, float c[2][8][4])
{
    extern __shared__ __align__(16) char smem[];
    const int t    = threadIdx.x;
    const int lane = t & 31;
    const int warp = t >> 5;
    const int wm   = warp >> 1;
    const int wn   = warp & 1;
    const uint32_t sm = smem_u32(smem);

    const int r0 = t >> 2;          // 0..63 (and +64)
    const int c0 = t & 3;           // 16B chunk within 64B row

    const uint32_t a_off = (uint32_t)((wm * 32 + (lane & 15)) * TSTR + (lane >> 4) * 16);
    const uint32_t b_off = (uint32_t)((wn * 64 + ((lane >> 4) * 8) + (lane & 7)) * TSTR + ((lane >> 3) & 1) * 16);

    const int nch = K / BK;
    load_stage(sm, Ah, Al, lda, Bh, Bl, ldb, 0, r0, c0);
    CP_COMMIT();

    int buf = 0;
    for (int ch = 0; ch < nch; ++ch) {
        if (ch + 1 < nch) {
            load_stage(sm + (buf ^ 1) * STAGE_B, Ah, Al, lda, Bh, Bl, ldb, (ch + 1) * BK, r0, c0);
            CP_COMMIT();
            CP_WAIT(1);
        } else {
            CP_WAIT(0);
        }
        __syncthreads();

        const uint32_t sb = sm + buf * STAGE_B;
        #pragma unroll
        for (int ks = 0; ks < 2; ++ks) {
            uint32_t ah[2][4], al[2][4], bh[8][2], bl[8][2];
            #pragma unroll
            for (int mt = 0; mt < 2; ++mt) {
                uint32_t ad = sb + a_off + (uint32_t)(mt * 16 * TSTR + ks * 32);
                ldmx4(ah[mt][0], ah[mt][1], ah[mt][2], ah[mt][3], ad + OFF_AHI);
                ldmx4(al[mt][0], al[mt][1], al[mt][2], al[mt][3], ad + OFF_ALO);
            }
            #pragma unroll
            for (int np = 0; np < 4; ++np) {
                uint32_t ad = sb + b_off + (uint32_t)(np * 16 * TSTR + ks * 32);
                ldmx4(bh[np * 2][0], bh[np * 2][1], bh[np * 2 + 1][0], bh[np * 2 + 1][1], ad + OFF_BHI);
                ldmx4(bl[np * 2][0], bl[np * 2][1], bl[np * 2 + 1][0], bl[np * 2 + 1][1], ad + OFF_BLO);
            }
            #pragma unroll
            for (int mt = 0; mt < 2; ++mt)
                #pragma unroll
                for (int nt = 0; nt < 8; ++nt) {
                    mma16816(c[mt][nt], ah[mt], bh[nt]);
                    mma16816(c[mt][nt], ah[mt], bl[nt]);
                    mma16816(c[mt][nt], al[mt], bh[nt]);
                }
        }
        __syncthreads();
        buf ^= 1;
    }
}

#define ACC_INIT(c) \
    _Pragma("unroll") for (int mt = 0; mt < 2; ++mt) \
    _Pragma("unroll") for (int nt = 0; nt < 8; ++nt) \
    _Pragma("unroll") for (int i = 0; i < 4; ++i) c[mt][nt][i] = 0.f

// ---------------------------------------------------------------------------
// Generic NT GEMM -> fp32 C (+bias)
// ---------------------------------------------------------------------------
__global__ __launch_bounds__(256) void gemm_nt_mma(
    const __nv_bfloat16* __restrict__ Ah, const __nv_bfloat16* __restrict__ Al, int lda,
    const __nv_bfloat16* __restrict__ Bh, const __nv_bfloat16* __restrict__ Bl, int ldb,
    float* __restrict__ C, int ldc, int K,
    const float* __restrict__ bias)
{
    const int m0 = blockIdx.y * 128, n0 = blockIdx.x * 128;
    float c[2][8][4];
    ACC_INIT(c);
    mma_mainloop(Ah + (size_t)m0 * lda, Al + (size_t)m0 * lda, lda,
                 Bh + (size_t)n0 * ldb, Bl + (size_t)n0 * ldb, ldb, K, c);

    const int lane = threadIdx.x & 31, warp = threadIdx.x >> 5;
    const int rb = m0 + (warp >> 1) * 32 + (lane >> 2);
    const int cb = n0 + (warp & 1) * 64 + (lane & 3) * 2;
    #pragma unroll
    for (int mt = 0; mt < 2; ++mt)
        #pragma unroll
        for (int nt = 0; nt < 8; ++nt) {
            int row = rb + mt * 16, col = cb + nt * 8;
            float b0 = bias ? bias[col] : 0.f, b1 = bias ? bias[col + 1] : 0.f;
            *(float2*)(C + (size_t)row * ldc + col)       = make_float2(c[mt][nt][0] + b0, c[mt][nt][1] + b1);
            *(float2*)(C + (size_t)(row + 8) * ldc + col) = make_float2(c[mt][nt][2] + b0, c[mt][nt][3] + b1);
        }
}

// ---------------------------------------------------------------------------
// Scores: S[z][m][n] = (Q.K)*SCALE + (1-mask[n])*-1e9  -> fp32 g_S
// ---------------------------------------------------------------------------
__global__ __launch_bounds__(256) void attn_scores_mma(const float* __restrict__ mask)
{
    const int z = blockIdx.z, b = z / HH, h = z % HH, hkv = h % HKV;
    const int m0 = blockIdx.y * 128, n0 = blockIdx.x * 128;
    const size_t aoff = ((size_t)(b * NN + m0) * HH + h) * HD;
    const size_t boff = ((size_t)(b * NN + n0) * HKV + hkv) * HD;
    float* C = g_S + (size_t)z * NN * NN;

    float c[2][8][4];
    ACC_INIT(c);
    mma_mainloop(g_Qh + aoff, g_Ql + aoff, HH * HD,
                 g_Kh + boff, g_Kl + boff, HKV * HD, HD, c);

    const int lane = threadIdx.x & 31, warp = threadIdx.x >> 5;
    const int rb = m0 + (warp >> 1) * 32 + (lane >> 2);
    const int cb = n0 + (warp & 1) * 64 + (lane & 3) * 2;
    #pragma unroll
    for (int mt = 0; mt < 2; ++mt)
        #pragma unroll
        for (int nt = 0; nt < 8; ++nt) {
            int row = rb + mt * 16, col = cb + nt * 8;
            float mb0 = (1.0f - mask[b * NN + col]) * -1e9f;
            float mb1 = (1.0f - mask[b * NN + col + 1]) * -1e9f;
            *(float2*)(C + (size_t)row * NN + col) =
                make_float2(c[mt][nt][0] * SCALE + mb0, c[mt][nt][1] * SCALE + mb1);
            *(float2*)(C + (size_t)(row + 8) * NN + col) =
                make_float2(c[mt][nt][2] * SCALE + mb0, c[mt][nt][3] * SCALE + mb1);
        }
}

// ---------------------------------------------------------------------------
// PV: ctx = P @ Vt^T -> bf16 hi/lo ctx
// ---------------------------------------------------------------------------
__global__ __launch_bounds__(256) void attn_pv_mma()
{
    const int z = blockIdx.z, b = z / HH, h = z % HH, hkv = h % HKV;
    const int m0 = blockIdx.y * 128;
    const size_t aoff = (size_t)z * NN * NN + (size_t)m0 * NN;
    const size_t boff = (size_t)(b * HKV + hkv) * HD * NN;

    float c[2][8][4];
    ACC_INIT(c);
    mma_mainloop(g_Ph + aoff, g_Pl + aoff, NN,
                 g_Vth + boff, g_Vtl + boff, NN, NN, c);

    const int lane = threadIdx.x & 31, warp = threadIdx.x >> 5;
    const int rb = (warp >> 1) * 32 + (lane >> 2);
    const int cb = (warp & 1) * 64 + (lane & 3) * 2;
    #pragma unroll
    for (int mt = 0; mt < 2; ++mt)
        #pragma unroll
        for (int nt = 0; nt < 8; ++nt) {
            int row = rb + mt * 16, col = cb + nt * 8;
            #pragma unroll
            for (int rr = 0; rr < 2; ++rr) {
                float v0 = c[mt][nt][rr * 2], v1 = c[mt][nt][rr * 2 + 1];
                __nv_bfloat16 h0, l0, h1, l1;
                split1(v0, h0, l0);
                split1(v1, h1, l1);
                size_t off = (size_t)(b * NN + m0 + row + rr * 8) * (HH * HD) + h * HD + col;
                *(uint32_t*)(g_ctxh + off) = packbf2(h0, h1);
                *(uint32_t*)(g_ctxl + off) = packbf2(l0, l1);
            }
        }
}

// ---------------------------------------------------------------------------
// Elementwise split: x -> xh, xl  (float4 vectorized)
// ---------------------------------------------------------------------------
__global__ void split_x(const float* __restrict__ src,
                        __nv_bfloat16* __restrict__ dh,
                        __nv_bfloat16* __restrict__ dl, int n4)
{
    int i = blockIdx.x * blockDim.x + threadIdx.x;
    if (i >= n4) return;
    float4 v = *(const float4*)(src + (size_t)i * 4);
    __nv_bfloat16 h0, l0, h1, l1, h2, l2, h3, l3;
    split1(v.x, h0, l0); split1(v.y, h1, l1);
    split1(v.z, h2, l2); split1(v.w, h3, l3);
    *(uint2*)(dh + (size_t)i * 4) = make_uint2(packbf2(h0, h1), packbf2(h2, h3));
    *(uint2*)(dl + (size_t)i * 4) = make_uint2(packbf2(l0, l1), packbf2(l2, l3));
}

// ---------------------------------------------------------------------------
// Transpose + split: dst[c*R + r] = src[r*C + c] as bf16 hi/lo
// ---------------------------------------------------------------------------
__global__ void transpose_split(const float* __restrict__ src,
                                __nv_bfloat16* __restrict__ dh,
                                __nv_bfloat16* __restrict__ dl, int R, int C)
{
    __shared__ float tile[32][33];
    int c0 = blockIdx.x * 32, r0 = blockIdx.y * 32;
    int tx = threadIdx.x, ty = threadIdx.y;
    #pragma unroll
    for (int i = ty; i < 32; i += 8)
        tile[i][tx] = src[(size_t)(r0 + i) * C + c0 + tx];
    __syncthreads();
    #pragma unroll
    for (int i = ty; i < 32; i += 8) {
        float v = tile[tx][i];
        __nv_bfloat16 h, l;
        split1(v, h, l);
        size_t off = (size_t)(c0 + i) * R + r0 + tx;
        dh[off] = h; dl[off] = l;
    }
}

// V: [b][n][hkv][hd] (inside g_QKV) -> Vt [b][hkv][hd][n] bf16 hi/lo
__global__ void transpose_v_split()
{
    __shared__ float tile[32][33];
    int z = blockIdx.z, b = z / HKV, hkv = z % HKV;
    int n0 = blockIdx.x * 32, d0 = blockIdx.y * 32;
    int tx = threadIdx.x, ty = threadIdx.y;
    #pragma unroll
    for (int i = ty; i < 32; i += 8)
        tile[i][tx] = g_QKV[(size_t)(b * NN + n0 + i) * QKVW + VOFF + hkv * HD + d0 + tx];
    __syncthreads();
    size_t base = (size_t)(b * HKV + hkv) * HD * NN;
    #pragma unroll
    for (int i = ty; i < 32; i += 8) {
        float v = tile[tx][i];
        __nv_bfloat16 h, l;
        split1(v, h, l);
        size_t off = base + (size_t)(d0 + i) * NN + n0 + tx;
        g_Vth[off] = h; g_Vtl[off] = l;
    }
}

// ---------------------------------------------------------------------------
// RoPE + split: g_QKV(fp32) -> Qh/Ql [b][n][h][hd], Kh/Kl [b][n][hkv][hd]
// ---------------------------------------------------------------------------
__global__ void rope_split(const float* __restrict__ cosb,
                           const float* __restrict__ sinb)
{
    int idx = blockIdx.x * blockDim.x + threadIdx.x;
    const int NQ = BB * NN * HH * (HD / 2);
    const int NK = BB * NN * HKV * (HD / 2);
    if (idx < NQ) {
        int i  = idx & 63;
        int h  = (idx >> 6) % HH;
        int bn = idx / (64 * HH);
        int n  = bn % NN;
        float cc = cosb[n * 64 + i], ss = sinb[n * 64 + i];
        const float* q = g_QKV + (size_t)bn * QKVW + h * HD;
        float t1 = q[i], t2 = q[i + 64];
        float r1 = t1 * cc + t2 * ss;
        float r2 = t2 * cc - t1 * ss;
        size_t o = ((size_t)bn * HH + h) * HD;
        __nv_bfloat16 h1, l1, h2, l2;
        split1(r1, h1, l1); split1(r2, h2, l2);
        g_Qh[o + i] = h1; g_Ql[o + i] = l1;
        g_Qh[o + i + 64] = h2; g_Ql[o + i + 64] = l2;
    } else {
        idx -= NQ;
        if (idx < NK) {
            int i  = idx & 63;
            int hk = (idx >> 6) % HKV;
            int bn = idx / (64 * HKV);
            int n  = bn % NN;
            float cc = cosb[n * 64 + i], ss = sinb[n * 64 + i];
            const float* k = g_QKV + (size_t)bn * QKVW + KOFF + hk * HD;
            float t1 = k[i], t2 = k[i + 64];
            float r1 = t1 * cc + t2 * ss;
            float r2 = t2 * cc - t1 * ss;
            size_t o = ((size_t)bn * HKV + hk) * HD;
            __nv_bfloat16 h1, l1, h2, l2;
            split1(r1, h1, l1); split1(r2, h2, l2);
            g_Kh[o + i] = h1; g_Kl[o + i] = l1;
            g_Kh[o + i + 64] = h2; g_Kl[o + i + 64] = l2;
        }
    }
}

// ---------------------------------------------------------------------------
// Row softmax: fp32 g_S -> bf16 hi/lo g_Ph/g_Pl
// ---------------------------------------------------------------------------
__global__ __launch_bounds__(256) void softmax_split()
{
    __shared__ float red[256];
    const float* p = g_S + (size_t)blockIdx.x * NN;
    __nv_bfloat16* ph = g_Ph + (size_t)blockIdx.x * NN;
    __nv_bfloat16* pl = g_Pl + (size_t)blockIdx.x * NN;
    const int t = threadIdx.x;

    float v[8];
    float m = -INFINITY;
    #pragma unroll
    for (int i = 0; i < 8; i++) { v[i] = p[t + i * 256]; m = fmaxf(m, v[i]); }
    red[t] = m; __syncthreads();
    for (int s = 128; s > 0; s >>= 1) {
        if (t < s) red[t] = fmaxf(red[t], red[t + s]);
        __syncthreads();
    }
    m = red[0]; __syncthreads();

    float sum = 0.f;
    #pragma unroll
    for (int i = 0; i < 8; i++) { v[i] = expf(v[i] - m); sum += v[i]; }
    red[t] = sum; __syncthreads();
    for (int s = 128; s > 0; s >>= 1) {
        if (t < s) red[t] += red[t + s];
        __syncthreads();
    }
    float inv = 1.0f / red[0];
    #pragma unroll
    for (int i = 0; i < 8; i++) {
        float pv = v[i] * inv;
        __nv_bfloat16 h, l;
        split1(pv, h, l);
        ph[t + i * 256] = h;
        pl[t + i * 256] = l;
    }
}

// ---------------------------------------------------------------------------
// Launch
// ---------------------------------------------------------------------------
extern "C" void kernel_launch(void* const* d_in, const int* in_sizes, int n_in,
                              void* d_out, int out_size)
{
    (void)in_sizes; (void)n_in; (void)out_size;

    const float* x    = (const float*)d_in[0];
    const float* cosb = (const float*)d_in[1];
    const float* sinb = (const float*)d_in[2];
    const float* mask = (const float*)d_in[3];
    const float* Wq   = (const float*)d_in[4];
    const float* Wkv  = (const float*)d_in[5];
    const float* Wo   = (const float*)d_in[6];
    const float* bo   = (const float*)d_in[7];
    float* out = (float*)d_out;

    float* pQKV;
    __nv_bfloat16 *pxh, *pxl, *pWTh, *pWTl, *pWoTh, *pWoTl, *pctxh, *pctxl;
    cudaGetSymbolAddress((void**)&pQKV,  g_QKV);
    cudaGetSymbolAddress((void**)&pxh,   g_xh);
    cudaGetSymbolAddress((void**)&pxl,   g_xl);
    cudaGetSymbolAddress((void**)&pWTh,  g_WTh);
    cudaGetSymbolAddress((void**)&pWTl,  g_WTl);
    cudaGetSymbolAddress((void**)&pWoTh, g_WoTh);
    cudaGetSymbolAddress((void**)&pWoTl, g_WoTl);
    cudaGetSymbolAddress((void**)&pctxh, g_ctxh);
    cudaGetSymbolAddress((void**)&pctxl, g_ctxl);

    cudaFuncSetAttribute(gemm_nt_mma,     cudaFuncAttributeMaxDynamicSharedMemorySize, SMEM_SZ);
    cudaFuncSetAttribute(attn_scores_mma, cudaFuncAttributeMaxDynamicSharedMemorySize, SMEM_SZ);
    cudaFuncSetAttribute(attn_pv_mma,     cudaFuncAttributeMaxDynamicSharedMemorySize, SMEM_SZ);

    const int M = BB * NN;   // 4096
    dim3 tb(32, 8);

    // x -> bf16 hi/lo
    {
        int n4 = BB * NN * DD / 4;
        split_x<<<(n4 + 255) / 256, 256>>>(x, pxh, pxl, n4);
    }
    // weight transposes + split
    transpose_split<<<dim3(DD / 32, DD / 32), tb>>>(Wq, pWTh, pWTl, DD, DD);
    transpose_split<<<dim3((2 * HKV * HD) / 32, DD / 32), tb>>>(Wkv, pWTh + (size_t)KOFF * DD, pWTl + (size_t)KOFF * DD, DD, 2 * HKV * HD);
    transpose_split<<<dim3(DD / 32, DD / 32), tb>>>(Wo, pWoTh, pWoTl, DD, DD);

    // QKV = x @ [Wq|Wkv] -> fp32 g_QKV
    gemm_nt_mma<<<dim3(QKVW / 128, M / 128), 256, SMEM_SZ>>>(
        pxh, pxl, DD, pWTh, pWTl, DD, pQKV, QKVW, DD, nullptr);

    // RoPE + split -> Qh/Ql, Kh/Kl
    {
        int total = BB * NN * HH * (HD / 2) + BB * NN * HKV * (HD / 2);
        rope_split<<<(total + 255) / 256, 256>>>(cosb, sinb);
    }
    // V transpose + split
    transpose_v_split<<<dim3(NN / 32, HD / 32, BB * HKV), tb>>>();

    // S = Q K^T * scale + maskbias (fp32)
    attn_scores_mma<<<dim3(NN / 128, NN / 128, BB * HH), 256, SMEM_SZ>>>(mask);

    // softmax -> P bf16 hi/lo
    softmax_split<<<BB * HH * NN, 256>>>();

    // ctx = P V -> bf16 hi/lo
    attn_pv_mma<<<dim3(1, NN / 128, BB * HH), 256, SMEM_SZ>>>();

    // out = ctx @ Wo + bo (fp32)
    gemm_nt_mma<<<dim3(DD / 128, M / 128), 256, SMEM_SZ>>>(
        pctxh, pctxl, HH * HD, pWoTh, pWoTl, DD, out, DD, DD, bo);
}

// round 6
// speedup vs baseline: 1.4551x; 1.4551x over previous
#include <cuda_runtime.h>
#include <cuda_bf16.h>
#include <math.h>
#include <cstdint>

// ---------------------------------------------------------------------------
// Problem constants
// ---------------------------------------------------------------------------
#define BB   2
#define NN   2048
#define DD   2048
#define HH   16
#define HKV  4
#define HD   128
#define GG   (HH / HKV)
#define QKVW (HH * HD + 2 * HKV * HD)     // 3072: Q(2048) | K(512) | V(512)
#define KOFF (HH * HD)                    // 2048
#define VOFF (HH * HD + HKV * HD)         // 2560
#define SCALE 0.08838834764831845f

#define BK 32                  // K-chunk (fp32 elements)
#define TSTR 80                // smem row stride bytes (64 data + 16 pad)
#define TILE_B (128 * TSTR)    // 10240 bytes per tile
#define STAGE_B (4 * TILE_B)   // 40960 bytes per stage (Ahi|Alo|Bhi|Blo)
#define SMEM_SZ (2 * STAGE_B)  // 81920 bytes, double buffered
#define OFF_AHI 0
#define OFF_ALO (TILE_B)
#define OFF_BHI (2 * TILE_B)
#define OFF_BLO (3 * TILE_B)

// ---------------------------------------------------------------------------
// Device scratch (__device__ globals — allocation-free)
// ---------------------------------------------------------------------------
__device__ float g_QKV[(size_t)BB * NN * QKVW];            // 48 MB
__device__ float g_WT [(size_t)QKVW * DD];                 // 24 MB
__device__ float g_WoT[(size_t)DD * DD];                   // 16 MB
__device__ float g_S  [(size_t)BB * HH * NN * NN];         // 512 MB
__device__ float g_Vt [(size_t)BB * HKV * HD * NN];        // 8 MB   [b][hkv][hd][n]
__device__ float g_ctx[(size_t)BB * NN * HH * HD];         // 32 MB

// ---------------------------------------------------------------------------
// PTX helpers (portable sm_80+ tensor path: ldmatrix + mma.sync bf16)
// ---------------------------------------------------------------------------
__device__ __forceinline__ uint32_t smem_u32(const void* p) {
    uint32_t a;
    asm("{ .reg .u64 t; cvta.to.shared.u64 t, %1; cvt.u32.u64 %0, t; }" : "=r"(a) : "l"(p));
    return a;
}
__device__ __forceinline__ void ldmx4(uint32_t& r0, uint32_t& r1, uint32_t& r2, uint32_t& r3, uint32_t addr) {
    asm volatile("ldmatrix.sync.aligned.m8n8.x4.shared.b16 {%0,%1,%2,%3}, [%4];"
                 : "=r"(r0), "=r"(r1), "=r"(r2), "=r"(r3) : "r"(addr));
}
__device__ __forceinline__ void mma16816(float* c, const uint32_t* a, const uint32_t* b) {
    asm volatile(
        "mma.sync.aligned.m16n8k16.row.col.f32.bf16.bf16.f32 "
        "{%0,%1,%2,%3}, {%4,%5,%6,%7}, {%8,%9}, {%0,%1,%2,%3};"
        : "+f"(c[0]), "+f"(c[1]), "+f"(c[2]), "+f"(c[3])
        : "r"(a[0]), "r"(a[1]), "r"(a[2]), "r"(a[3]), "r"(b[0]), "r"(b[1]));
}

__device__ __forceinline__ void split4(float4 v, uint2& hi, uint2& lo) {
    __nv_bfloat16 hx = __float2bfloat16(v.x), hy = __float2bfloat16(v.y),
                  hz = __float2bfloat16(v.z), hw = __float2bfloat16(v.w);
    __nv_bfloat162 h01 = __halves2bfloat162(hx, hy), h23 = __halves2bfloat162(hz, hw);
    __nv_bfloat16 lx = __float2bfloat16(v.x - __bfloat162float(hx));
    __nv_bfloat16 ly = __float2bfloat16(v.y - __bfloat162float(hy));
    __nv_bfloat16 lz = __float2bfloat16(v.z - __bfloat162float(hz));
    __nv_bfloat16 lw = __float2bfloat16(v.w - __bfloat162float(hw));
    __nv_bfloat162 l01 = __halves2bfloat162(lx, ly), l23 = __halves2bfloat162(lz, lw);
    hi = make_uint2(*(uint32_t*)&h01, *(uint32_t*)&h23);
    lo = make_uint2(*(uint32_t*)&l01, *(uint32_t*)&l23);
}

// convert prefetched registers -> one smem stage (4 tiles)
__device__ __forceinline__ void store_stage(char* sb, int t, const float4* pa, const float4* pb) {
    #pragma unroll
    for (int i = 0; i < 4; ++i) {
        int idx = t + i * 256, row = idx >> 3, c4 = idx & 7;
        uint32_t off = (uint32_t)(row * TSTR + c4 * 8);
        uint2 hi, lo;
        split4(pa[i], hi, lo);
        *(uint2*)(sb + OFF_AHI + off) = hi;
        *(uint2*)(sb + OFF_ALO + off) = lo;
        split4(pb[i], hi, lo);
        *(uint2*)(sb + OFF_BHI + off) = hi;
        *(uint2*)(sb + OFF_BLO + off) = lo;
    }
}

// ---------------------------------------------------------------------------
// Mainloop: acc[2][8][4] += A[128,K] @ B[128,K]^T  (bf16 hi/lo split, fp32 acc)
// 256 threads; warps 4(M) x 2(N); warp tile 32x64.
// Double-buffered smem, ONE __syncthreads per chunk; next-chunk LDG issued
// before the MMA phase so global latency hides under tensor work.
// ---------------------------------------------------------------------------
__device__ __forceinline__ void mma_mainloop(
    const float* __restrict__ A, int lda,
    const float* __restrict__ B, int ldb, int K,
    float c[2][8][4])
{
    extern __shared__ __align__(16) char smem[];
    const int t    = threadIdx.x;
    const int lane = t & 31;
    const int warp = t >> 5;
    const int wm   = warp >> 1;   // 0..3
    const int wn   = warp & 1;    // 0..1
    const uint32_t sm = smem_u32(smem);

    const uint32_t a_off = (uint32_t)((wm * 32 + (lane & 15)) * TSTR + (lane >> 4) * 16);
    const uint32_t b_off = (uint32_t)(OFF_BHI + (wn * 64 + ((lane >> 4) * 8) + (lane & 7)) * TSTR + ((lane >> 3) & 1) * 16);

    float4 pa[4], pb[4];
    const int nch = K / BK;

    // chunk 0: load + convert + store to stage 0
    #pragma unroll
    for (int i = 0; i < 4; ++i) {
        int idx = t + i * 256, row = idx >> 3, c4 = idx & 7;
        pa[i] = *(const float4*)(A + (size_t)row * lda + c4 * 4);
        pb[i] = *(const float4*)(B + (size_t)row * ldb + c4 * 4);
    }
    store_stage(smem, t, pa, pb);
    __syncthreads();

    uint32_t buf = 0;
    for (int ch = 0; ch < nch; ++ch) {
        // issue next chunk's global loads early (latency hides under MMAs)
        if (ch + 1 < nch) {
            const int k0 = (ch + 1) * BK;
            #pragma unroll
            for (int i = 0; i < 4; ++i) {
                int idx = t + i * 256, row = idx >> 3, c4 = idx & 7;
                pa[i] = *(const float4*)(A + (size_t)row * lda + k0 + c4 * 4);
                pb[i] = *(const float4*)(B + (size_t)row * ldb + k0 + c4 * 4);
            }
        }

        // MMA phase on current buffer
        const uint32_t sb = sm + buf * STAGE_B;
        #pragma unroll
        for (int ks = 0; ks < 2; ++ks) {
            uint32_t ah[2][4], al[2][4], bh[8][2], bl[8][2];
            #pragma unroll
            for (int mt = 0; mt < 2; ++mt) {
                uint32_t ad = sb + a_off + (uint32_t)(mt * 16 * TSTR + ks * 32);
                ldmx4(ah[mt][0], ah[mt][1], ah[mt][2], ah[mt][3], ad + OFF_AHI);
                ldmx4(al[mt][0], al[mt][1], al[mt][2], al[mt][3], ad + OFF_ALO);
            }
            #pragma unroll
            for (int np = 0; np < 4; ++np) {
                uint32_t ad = sb + b_off + (uint32_t)(np * 16 * TSTR + ks * 32);
                ldmx4(bh[np * 2][0], bh[np * 2][1], bh[np * 2 + 1][0], bh[np * 2 + 1][1], ad);
                ldmx4(bl[np * 2][0], bl[np * 2][1], bl[np * 2 + 1][0], bl[np * 2 + 1][1], ad + TILE_B);
            }
            #pragma unroll
            for (int mt = 0; mt < 2; ++mt)
                #pragma unroll
                for (int nt = 0; nt < 8; ++nt) {
                    mma16816(c[mt][nt], ah[mt], bh[nt]);
                    mma16816(c[mt][nt], ah[mt], bl[nt]);
                    mma16816(c[mt][nt], al[mt], bh[nt]);
                }
        }

        // convert + store next chunk into the other buffer
        if (ch + 1 < nch)
            store_stage(smem + (buf ^ 1) * STAGE_B, t, pa, pb);
        __syncthreads();
        buf ^= 1;
    }
}

#define ACC_INIT(c) \
    _Pragma("unroll") for (int mt = 0; mt < 2; ++mt) \
    _Pragma("unroll") for (int nt = 0; nt < 8; ++nt) \
    _Pragma("unroll") for (int i = 0; i < 4; ++i) c[mt][nt][i] = 0.f

// ---------------------------------------------------------------------------
// Generic NT GEMM: C[m0+i][n0+j] = sum_k A[m0+i][k]*B[n0+j][k] (+bias)
// ---------------------------------------------------------------------------
__global__ __launch_bounds__(256) void gemm_nt_mma(
    const float* __restrict__ A, int lda,
    const float* __restrict__ B, int ldb,
    float* __restrict__ C, int ldc, int K,
    const float* __restrict__ bias)
{
    const int m0 = blockIdx.y * 128, n0 = blockIdx.x * 128;
    float c[2][8][4];
    ACC_INIT(c);

    mma_mainloop(A + (size_t)m0 * lda, lda, B + (size_t)n0 * ldb, ldb, K, c);

    const int lane = threadIdx.x & 31, warp = threadIdx.x >> 5;
    const int rb = m0 + (warp >> 1) * 32 + (lane >> 2);
    const int cb = n0 + (warp & 1) * 64 + (lane & 3) * 2;
    #pragma unroll
    for (int mt = 0; mt < 2; ++mt)
        #pragma unroll
        for (int nt = 0; nt < 8; ++nt) {
            int row = rb + mt * 16, col = cb + nt * 8;
            float b0 = bias ? bias[col] : 0.f, b1 = bias ? bias[col + 1] : 0.f;
            *(float2*)(C + (size_t)row * ldc + col)       = make_float2(c[mt][nt][0] + b0, c[mt][nt][1] + b1);
            *(float2*)(C + (size_t)(row + 8) * ldc + col) = make_float2(c[mt][nt][2] + b0, c[mt][nt][3] + b1);
        }
}

// ---------------------------------------------------------------------------
// Scores: S[z][m][n] = (Q_h[m].K_hkv[n])*SCALE + (1-mask[n])*-1e9
// ---------------------------------------------------------------------------
__global__ __launch_bounds__(256) void attn_scores_mma(
    const float* __restrict__ mask, const float* __restrict__ qkv)
{
    const int z = blockIdx.z, b = z / HH, h = z % HH, hkv = h % HKV;
    const int m0 = blockIdx.y * 128, n0 = blockIdx.x * 128;
    const float* A = qkv + (size_t)(b * NN + m0) * QKVW + h * HD;
    const float* B = qkv + (size_t)(b * NN + n0) * QKVW + KOFF + hkv * HD;
    float* C = g_S + (size_t)z * NN * NN;

    float c[2][8][4];
    ACC_INIT(c);

    mma_mainloop(A, QKVW, B, QKVW, HD, c);

    const int lane = threadIdx.x & 31, warp = threadIdx.x >> 5;
    const int rb = m0 + (warp >> 1) * 32 + (lane >> 2);
    const int cb = n0 + (warp & 1) * 64 + (lane & 3) * 2;
    #pragma unroll
    for (int mt = 0; mt < 2; ++mt)
        #pragma unroll
        for (int nt = 0; nt < 8; ++nt) {
            int row = rb + mt * 16, col = cb + nt * 8;
            float mb0 = (1.0f - mask[b * NN + col]) * -1e9f;
            float mb1 = (1.0f - mask[b * NN + col + 1]) * -1e9f;
            *(float2*)(C + (size_t)row * NN + col) =
                make_float2(c[mt][nt][0] * SCALE + mb0, c[mt][nt][1] * SCALE + mb1);
            *(float2*)(C + (size_t)(row + 8) * NN + col) =
                make_float2(c[mt][nt][2] * SCALE + mb0, c[mt][nt][3] * SCALE + mb1);
        }
}

// ---------------------------------------------------------------------------
// PV: ctx[b][m][h*HD+d] = sum_n P[z][m][n] * Vt[b][hkv][d][n]
// ---------------------------------------------------------------------------
__global__ __launch_bounds__(256) void attn_pv_mma()
{
    const int z = blockIdx.z, b = z / HH, h = z % HH, hkv = h % HKV;
    const int m0 = blockIdx.y * 128;
    const float* A = g_S + (size_t)z * NN * NN + (size_t)m0 * NN;
    const float* B = g_Vt + (size_t)(b * HKV + hkv) * HD * NN;

    float c[2][8][4];
    ACC_INIT(c);

    mma_mainloop(A, NN, B, NN, NN, c);

    const int lane = threadIdx.x & 31, warp = threadIdx.x >> 5;
    const int rb = (warp >> 1) * 32 + (lane >> 2);
    const int cb = (warp & 1) * 64 + (lane & 3) * 2;
    #pragma unroll
    for (int mt = 0; mt < 2; ++mt)
        #pragma unroll
        for (int nt = 0; nt < 8; ++nt) {
            int row = rb + mt * 16, col = cb + nt * 8;
            float* p0 = g_ctx + (size_t)(b * NN + m0 + row) * (HH * HD) + h * HD + col;
            float* p1 = g_ctx + (size_t)(b * NN + m0 + row + 8) * (HH * HD) + h * HD + col;
            *(float2*)p0 = make_float2(c[mt][nt][0], c[mt][nt][1]);
            *(float2*)p1 = make_float2(c[mt][nt][2], c[mt][nt][3]);
        }
}

// ---------------------------------------------------------------------------
// Transposes
// ---------------------------------------------------------------------------
__global__ void transpose_f32(const float* __restrict__ src, float* __restrict__ dst,
                              int R, int C)   // dst[c*R + r] = src[r*C + c]
{
    __shared__ float tile[32][33];
    int c0 = blockIdx.x * 32, r0 = blockIdx.y * 32;
    int tx = threadIdx.x, ty = threadIdx.y;
    #pragma unroll
    for (int i = ty; i < 32; i += 8)
        tile[i][tx] = src[(size_t)(r0 + i) * C + c0 + tx];
    __syncthreads();
    #pragma unroll
    for (int i = ty; i < 32; i += 8)
        dst[(size_t)(c0 + i) * R + r0 + tx] = tile[tx][i];
}

__global__ void transpose_v(const float* __restrict__ qkv)
{
    __shared__ float tile[32][33];
    int z = blockIdx.z, b = z / HKV, hkv = z % HKV;
    int n0 = blockIdx.x * 32, d0 = blockIdx.y * 32;
    int tx = threadIdx.x, ty = threadIdx.y;
    #pragma unroll
    for (int i = ty; i < 32; i += 8)
        tile[i][tx] = qkv[(size_t)(b * NN + n0 + i) * QKVW + VOFF + hkv * HD + d0 + tx];
    __syncthreads();
    float* dst = g_Vt + (size_t)(b * HKV + hkv) * HD * NN;
    #pragma unroll
    for (int i = ty; i < 32; i += 8)
        dst[(size_t)(d0 + i) * NN + n0 + tx] = tile[tx][i];
}

// ---------------------------------------------------------------------------
// RoPE in-place on g_QKV (Q and K parts). cos/sin: [N,64]
// ---------------------------------------------------------------------------
__global__ void rope_kernel(const float* __restrict__ cosb,
                            const float* __restrict__ sinb,
                            float* __restrict__ qkv)
{
    int idx = blockIdx.x * blockDim.x + threadIdx.x;
    const int NQ = BB * NN * HH * (HD / 2);
    const int NK = BB * NN * HKV * (HD / 2);
    if (idx < NQ) {
        int i  = idx & 63;
        int h  = (idx >> 6) % HH;
        int bn = idx / (64 * HH);
        int n  = bn % NN;
        float c = cosb[n * 64 + i], s = sinb[n * 64 + i];
        float* q = qkv + (size_t)bn * QKVW + h * HD;
        float t1 = q[i], t2 = q[i + 64];
        q[i]      = t1 * c + t2 * s;
        q[i + 64] = t2 * c - t1 * s;
    } else {
        idx -= NQ;
        if (idx < NK) {
            int i  = idx & 63;
            int hk = (idx >> 6) % HKV;
            int bn = idx / (64 * HKV);
            int n  = bn % NN;
            float c = cosb[n * 64 + i], s = sinb[n * 64 + i];
            float* k = qkv + (size_t)bn * QKVW + KOFF + hk * HD;
            float t1 = k[i], t2 = k[i + 64];
            k[i]      = t1 * c + t2 * s;
            k[i + 64] = t2 * c - t1 * s;
        }
    }
}

// ---------------------------------------------------------------------------
// Row softmax in-place on g_S
// ---------------------------------------------------------------------------
__global__ __launch_bounds__(256) void softmax_rows()
{
    __shared__ float red[256];
    float* p = g_S + (size_t)blockIdx.x * NN;
    const int t = threadIdx.x;

    float v[8];
    float m = -INFINITY;
    #pragma unroll
    for (int i = 0; i < 8; i++) { v[i] = p[t + i * 256]; m = fmaxf(m, v[i]); }
    red[t] = m; __syncthreads();
    for (int s = 128; s > 0; s >>= 1) {
        if (t < s) red[t] = fmaxf(red[t], red[t + s]);
        __syncthreads();
    }
    m = red[0]; __syncthreads();

    float sum = 0.f;
    #pragma unroll
    for (int i = 0; i < 8; i++) { v[i] = expf(v[i] - m); sum += v[i]; }
    red[t] = sum; __syncthreads();
    for (int s = 128; s > 0; s >>= 1) {
        if (t < s) red[t] += red[t + s];
        __syncthreads();
    }
    float inv = 1.0f / red[0];
    #pragma unroll
    for (int i = 0; i < 8; i++) p[t + i * 256] = v[i] * inv;
}

// ---------------------------------------------------------------------------
// Launch
// ---------------------------------------------------------------------------
extern "C" void kernel_launch(void* const* d_in, const int* in_sizes, int n_in,
                              void* d_out, int out_size)
{
    (void)in_sizes; (void)n_in; (void)out_size;

    const float* x    = (const float*)d_in[0];
    const float* cosb = (const float*)d_in[1];
    const float* sinb = (const float*)d_in[2];
    const float* mask = (const float*)d_in[3];
    const float* Wq   = (const float*)d_in[4];
    const float* Wkv  = (const float*)d_in[5];
    const float* Wo   = (const float*)d_in[6];
    const float* bo   = (const float*)d_in[7];
    float* out = (float*)d_out;

    float *pQKV, *pWT, *pWoT, *pCtx;
    cudaGetSymbolAddress((void**)&pQKV, g_QKV);
    cudaGetSymbolAddress((void**)&pWT,  g_WT);
    cudaGetSymbolAddress((void**)&pWoT, g_WoT);
    cudaGetSymbolAddress((void**)&pCtx, g_ctx);

    cudaFuncSetAttribute(gemm_nt_mma,     cudaFuncAttributeMaxDynamicSharedMemorySize, SMEM_SZ);
    cudaFuncSetAttribute(attn_scores_mma, cudaFuncAttributeMaxDynamicSharedMemorySize, SMEM_SZ);
    cudaFuncSetAttribute(attn_pv_mma,     cudaFuncAttributeMaxDynamicSharedMemorySize, SMEM_SZ);

    const int M = BB * NN;   // 4096
    dim3 tb(32, 8);

    // Weight transposes: WT[j][k] = [Wq|Wkv][k][j], WoT[j][k] = Wo[k][j]
    transpose_f32<<<dim3(DD / 32, DD / 32), tb>>>(Wq, pWT, DD, DD);
    transpose_f32<<<dim3((2 * HKV * HD) / 32, DD / 32), tb>>>(Wkv, pWT + (size_t)KOFF * DD, DD, 2 * HKV * HD);
    transpose_f32<<<dim3(DD / 32, DD / 32), tb>>>(Wo, pWoT, DD, DD);

    // QKV = x @ [Wq|Wkv] : [4096,2048] x [3072,2048]
    gemm_nt_mma<<<dim3(QKVW / 128, M / 128), 256, SMEM_SZ>>>(x, DD, pWT, DD, pQKV, QKVW, DD, nullptr);

    // RoPE
    {
        int total = BB * NN * HH * (HD / 2) + BB * NN * HKV * (HD / 2);
        rope_kernel<<<(total + 255) / 256, 256>>>(cosb, sinb, pQKV);
    }

    // S = Q K^T * scale + maskbias
    attn_scores_mma<<<dim3(NN / 128, NN / 128, BB * HH), 256, SMEM_SZ>>>(mask, pQKV);

    // V transpose for NT PV
    transpose_v<<<dim3(NN / 32, HD / 32, BB * HKV), tb>>>(pQKV);

    // softmax
    softmax_rows<<<BB * HH * NN, 256>>>();

    // ctx = P V
    attn_pv_mma<<<dim3(1, NN / 128, BB * HH), 256, SMEM_SZ>>>();

    // out = ctx @ Wo + bo
    gemm_nt_mma<<<dim3(DD / 128, M / 128), 256, SMEM_SZ>>>(pCtx, HH * HD, pWoT, DD, out, DD, DD, bo);
}

// round 7
// speedup vs baseline: 1.7017x; 1.1695x over previous
#include <cuda_runtime.h>
#include <cuda_bf16.h>
#include <math.h>
#include <cstdint>

// ---------------------------------------------------------------------------
// Problem constants
// ---------------------------------------------------------------------------
#define BB   2
#define NN   2048
#define DD   2048
#define HH   16
#define HKV  4
#define HD   128
#define GG   (HH / HKV)
#define QKVW (HH * HD + 2 * HKV * HD)     // 3072: Q(2048) | K(512) | V(512)
#define KOFF (HH * HD)                    // 2048
#define VOFF (HH * HD + HKV * HD)         // 2560
#define SCALE 0.08838834764831845f

#define BK 32                  // K-chunk (fp32 elements) for gemm
#define TSTR 80                // gemm smem row stride bytes (64 data + 16 pad)
#define TILE_B (128 * TSTR)
#define STAGE_B (4 * TILE_B)
#define SMEM_SZ (2 * STAGE_B)  // 81920 (gemm)
#define OFF_AHI 0
#define OFF_ALO (TILE_B)
#define OFF_BHI (2 * TILE_B)
#define OFF_BLO (3 * TILE_B)

// flash-attention smem layout (bytes)
#define KSTR 272               // 128 bf16 cols (256B) + 16 pad
#define VSTR 144               // 64 bf16 cols (128B) + 16 pad
#define F_QHI 0
#define F_QLO (F_QHI + 128 * KSTR)    // 34816
#define F_KHI (F_QLO + 128 * KSTR)    // 69632
#define F_KLO (F_KHI + 64 * KSTR)     // 87040
#define F_VHI (F_KLO + 64 * KSTR)     // 104448
#define F_VLO (F_VHI + 128 * VSTR)    // 122880
#define F_PHI (F_VLO + 128 * VSTR)    // 141312
#define F_PLO (F_PHI + 128 * VSTR)    // 159744
#define F_SZ  (F_PLO + 128 * VSTR)    // 178176

// ---------------------------------------------------------------------------
// Device scratch
// ---------------------------------------------------------------------------
__device__ float g_QKV[(size_t)BB * NN * QKVW];            // 48 MB
__device__ float g_WT [(size_t)QKVW * DD];                 // 24 MB
__device__ float g_WoT[(size_t)DD * DD];                   // 16 MB
__device__ float g_Vt [(size_t)BB * HKV * HD * NN];        // 8 MB  [b][hkv][hd][n]
__device__ float g_ctx[(size_t)BB * NN * HH * HD];         // 32 MB

// ---------------------------------------------------------------------------
// PTX helpers
// ---------------------------------------------------------------------------
__device__ __forceinline__ uint32_t smem_u32(const void* p) {
    uint32_t a;
    asm("{ .reg .u64 t; cvta.to.shared.u64 t, %1; cvt.u32.u64 %0, t; }" : "=r"(a) : "l"(p));
    return a;
}
__device__ __forceinline__ void ldmx4(uint32_t& r0, uint32_t& r1, uint32_t& r2, uint32_t& r3, uint32_t addr) {
    asm volatile("ldmatrix.sync.aligned.m8n8.x4.shared.b16 {%0,%1,%2,%3}, [%4];"
                 : "=r"(r0), "=r"(r1), "=r"(r2), "=r"(r3) : "r"(addr));
}
__device__ __forceinline__ void mma16816(float* c, const uint32_t* a, const uint32_t* b) {
    asm volatile(
        "mma.sync.aligned.m16n8k16.row.col.f32.bf16.bf16.f32 "
        "{%0,%1,%2,%3}, {%4,%5,%6,%7}, {%8,%9}, {%0,%1,%2,%3};"
        : "+f"(c[0]), "+f"(c[1]), "+f"(c[2]), "+f"(c[3])
        : "r"(a[0]), "r"(a[1]), "r"(a[2]), "r"(a[3]), "r"(b[0]), "r"(b[1]));
}

__device__ __forceinline__ void split4(float4 v, uint2& hi, uint2& lo) {
    __nv_bfloat16 hx = __float2bfloat16(v.x), hy = __float2bfloat16(v.y),
                  hz = __float2bfloat16(v.z), hw = __float2bfloat16(v.w);
    __nv_bfloat162 h01 = __halves2bfloat162(hx, hy), h23 = __halves2bfloat162(hz, hw);
    __nv_bfloat16 lx = __float2bfloat16(v.x - __bfloat162float(hx));
    __nv_bfloat16 ly = __float2bfloat16(v.y - __bfloat162float(hy));
    __nv_bfloat16 lz = __float2bfloat16(v.z - __bfloat162float(hz));
    __nv_bfloat16 lw = __float2bfloat16(v.w - __bfloat162float(hw));
    __nv_bfloat162 l01 = __halves2bfloat162(lx, ly), l23 = __halves2bfloat162(lz, lw);
    hi = make_uint2(*(uint32_t*)&h01, *(uint32_t*)&h23);
    lo = make_uint2(*(uint32_t*)&l01, *(uint32_t*)&l23);
}
__device__ __forceinline__ void split2(float a, float b, uint32_t& hi, uint32_t& lo) {
    __nv_bfloat16 ha = __float2bfloat16(a), hb = __float2bfloat16(b);
    __nv_bfloat16 la = __float2bfloat16(a - __bfloat162float(ha));
    __nv_bfloat16 lb = __float2bfloat16(b - __bfloat162float(hb));
    __nv_bfloat162 hp = __halves2bfloat162(ha, hb), lp = __halves2bfloat162(la, lb);
    hi = *(uint32_t*)&hp; lo = *(uint32_t*)&lp;
}

// gemm stage store (unchanged from R6)
__device__ __forceinline__ void store_stage(char* sb, int t, const float4* pa, const float4* pb) {
    #pragma unroll
    for (int i = 0; i < 4; ++i) {
        int idx = t + i * 256, row = idx >> 3, c4 = idx & 7;
        uint32_t off = (uint32_t)(row * TSTR + c4 * 8);
        uint2 hi, lo;
        split4(pa[i], hi, lo);
        *(uint2*)(sb + OFF_AHI + off) = hi;
        *(uint2*)(sb + OFF_ALO + off) = lo;
        split4(pb[i], hi, lo);
        *(uint2*)(sb + OFF_BHI + off) = hi;
        *(uint2*)(sb + OFF_BLO + off) = lo;
    }
}

// ---------------------------------------------------------------------------
// GEMM mainloop (unchanged from R6 — double-buffered, 1 barrier/chunk)
// ---------------------------------------------------------------------------
__device__ __forceinline__ void mma_mainloop(
    const float* __restrict__ A, int lda,
    const float* __restrict__ B, int ldb, int K,
    float c[2][8][4])
{
    extern __shared__ __align__(16) char smem[];
    const int t    = threadIdx.x;
    const int lane = t & 31;
    const int warp = t >> 5;
    const int wm   = warp >> 1;
    const int wn   = warp & 1;
    const uint32_t sm = smem_u32(smem);

    const uint32_t a_off = (uint32_t)((wm * 32 + (lane & 15)) * TSTR + (lane >> 4) * 16);
    const uint32_t b_off = (uint32_t)(OFF_BHI + (wn * 64 + ((lane >> 4) * 8) + (lane & 7)) * TSTR + ((lane >> 3) & 1) * 16);

    float4 pa[4], pb[4];
    const int nch = K / BK;

    #pragma unroll
    for (int i = 0; i < 4; ++i) {
        int idx = t + i * 256, row = idx >> 3, c4 = idx & 7;
        pa[i] = *(const float4*)(A + (size_t)row * lda + c4 * 4);
        pb[i] = *(const float4*)(B + (size_t)row * ldb + c4 * 4);
    }
    store_stage(smem, t, pa, pb);
    __syncthreads();

    uint32_t buf = 0;
    for (int ch = 0; ch < nch; ++ch) {
        if (ch + 1 < nch) {
            const int k0 = (ch + 1) * BK;
            #pragma unroll
            for (int i = 0; i < 4; ++i) {
                int idx = t + i * 256, row = idx >> 3, c4 = idx & 7;
                pa[i] = *(const float4*)(A + (size_t)row * lda + k0 + c4 * 4);
                pb[i] = *(const float4*)(B + (size_t)row * ldb + k0 + c4 * 4);
            }
        }
        const uint32_t sb = sm + buf * STAGE_B;
        #pragma unroll
        for (int ks = 0; ks < 2; ++ks) {
            uint32_t ah[2][4], al[2][4], bh[8][2], bl[8][2];
            #pragma unroll
            for (int mt = 0; mt < 2; ++mt) {
                uint32_t ad = sb + a_off + (uint32_t)(mt * 16 * TSTR + ks * 32);
                ldmx4(ah[mt][0], ah[mt][1], ah[mt][2], ah[mt][3], ad + OFF_AHI);
                ldmx4(al[mt][0], al[mt][1], al[mt][2], al[mt][3], ad + OFF_ALO);
            }
            #pragma unroll
            for (int np = 0; np < 4; ++np) {
                uint32_t ad = sb + b_off + (uint32_t)(np * 16 * TSTR + ks * 32);
                ldmx4(bh[np * 2][0], bh[np * 2][1], bh[np * 2 + 1][0], bh[np * 2 + 1][1], ad);
                ldmx4(bl[np * 2][0], bl[np * 2][1], bl[np * 2 + 1][0], bl[np * 2 + 1][1], ad + TILE_B);
            }
            #pragma unroll
            for (int mt = 0; mt < 2; ++mt)
                #pragma unroll
                for (int nt = 0; nt < 8; ++nt) {
                    mma16816(c[mt][nt], ah[mt], bh[nt]);
                    mma16816(c[mt][nt], ah[mt], bl[nt]);
                    mma16816(c[mt][nt], al[mt], bh[nt]);
                }
        }
        if (ch + 1 < nch)
            store_stage(smem + (buf ^ 1) * STAGE_B, t, pa, pb);
        __syncthreads();
        buf ^= 1;
    }
}

#define ACC_INIT(c) \
    _Pragma("unroll") for (int mt = 0; mt < 2; ++mt) \
    _Pragma("unroll") for (int nt = 0; nt < 8; ++nt) \
    _Pragma("unroll") for (int i = 0; i < 4; ++i) c[mt][nt][i] = 0.f

// ---------------------------------------------------------------------------
// Generic NT GEMM (unchanged from R6)
// ---------------------------------------------------------------------------
__global__ __launch_bounds__(256) void gemm_nt_mma(
    const float* __restrict__ A, int lda,
    const float* __restrict__ B, int ldb,
    float* __restrict__ C, int ldc, int K,
    const float* __restrict__ bias)
{
    const int m0 = blockIdx.y * 128, n0 = blockIdx.x * 128;
    float c[2][8][4];
    ACC_INIT(c);

    mma_mainloop(A + (size_t)m0 * lda, lda, B + (size_t)n0 * ldb, ldb, K, c);

    const int lane = threadIdx.x & 31, warp = threadIdx.x >> 5;
    const int rb = m0 + (warp >> 1) * 32 + (lane >> 2);
    const int cb = n0 + (warp & 1) * 64 + (lane & 3) * 2;
    #pragma unroll
    for (int mt = 0; mt < 2; ++mt)
        #pragma unroll
        for (int nt = 0; nt < 8; ++nt) {
            int row = rb + mt * 16, col = cb + nt * 8;
            float b0 = bias ? bias[col] : 0.f, b1 = bias ? bias[col + 1] : 0.f;
            *(float2*)(C + (size_t)row * ldc + col)       = make_float2(c[mt][nt][0] + b0, c[mt][nt][1] + b1);
            *(float2*)(C + (size_t)(row + 8) * ldc + col) = make_float2(c[mt][nt][2] + b0, c[mt][nt][3] + b1);
        }
}

// ---------------------------------------------------------------------------
// Fused flash attention: per CTA = (b,h) x 128 query rows.
// Loops over 32 key-chunks of 64: S=QK^T (3-MMA hi/lo), online softmax,
// O += P V (3-MMA hi/lo). Warp owns 16 full rows -> intra-warp row stats.
// ---------------------------------------------------------------------------
__global__ __launch_bounds__(256) void flash_attn(
    const float* __restrict__ mask, const float* __restrict__ qkv)
{
    extern __shared__ __align__(16) char smem[];
    const int z = blockIdx.z, b = z / HH, h = z % HH, hkv = h % HKV;
    const int m0 = blockIdx.y * 128;
    const int t = threadIdx.x, lane = t & 31, w = t >> 5;
    const uint32_t sm = smem_u32(smem);

    // ---- load Q tile [128 x HD] -> bf16 hi/lo smem (once) ----
    {
        const float* Qg = qkv + (size_t)(b * NN + m0) * QKVW + h * HD;
        #pragma unroll
        for (int i = 0; i < 16; ++i) {
            int idx = t + i * 256, row = idx >> 5, c4 = idx & 31;
            float4 v = *(const float4*)(Qg + (size_t)row * QKVW + c4 * 4);
            uint2 hi, lo;
            split4(v, hi, lo);
            uint32_t off = (uint32_t)(row * KSTR + c4 * 8);
            *(uint2*)(smem + F_QHI + off) = hi;
            *(uint2*)(smem + F_QLO + off) = lo;
        }
    }

    float co[16][4];
    #pragma unroll
    for (int nt = 0; nt < 16; ++nt)
        #pragma unroll
        for (int i = 0; i < 4; ++i) co[nt][i] = 0.f;
    float m0r = -INFINITY, m1r = -INFINITY;   // running max (rows r, r+8)
    float l0r = 0.f, l1r = 0.f;               // running sum

    // fragment addresses
    const uint32_t qa_off = (uint32_t)((w * 16 + (lane & 15)) * KSTR + (lane >> 4) * 16);
    const uint32_t kb_base = (uint32_t)(((lane >> 4) * 8 + (lane & 7)) * KSTR + ((lane >> 3) & 1) * 16);
    const uint32_t pa_off = (uint32_t)((w * 16 + (lane & 15)) * VSTR + (lane >> 4) * 16);
    const uint32_t vb_base = (uint32_t)(((lane >> 4) * 8 + (lane & 7)) * VSTR + ((lane >> 3) & 1) * 16);

    __syncthreads();

    for (int ch = 0; ch < NN / 64; ++ch) {
        const int n0 = ch * 64;
        // ---- load K chunk [64 x HD] ----
        {
            const float* Kg = qkv + (size_t)(b * NN + n0) * QKVW + KOFF + hkv * HD;
            #pragma unroll
            for (int i = 0; i < 8; ++i) {
                int idx = t + i * 256, row = idx >> 5, c4 = idx & 31;
                float4 v = *(const float4*)(Kg + (size_t)row * QKVW + c4 * 4);
                uint2 hi, lo;
                split4(v, hi, lo);
                uint32_t off = (uint32_t)(row * KSTR + c4 * 8);
                *(uint2*)(smem + F_KHI + off) = hi;
                *(uint2*)(smem + F_KLO + off) = lo;
            }
        }
        // ---- load V chunk: Vt[d][n0..n0+64) -> [128 x 64] ----
        {
            const float* Vg = g_Vt + (size_t)(b * HKV + hkv) * HD * NN + n0;
            #pragma unroll
            for (int i = 0; i < 8; ++i) {
                int idx = t + i * 256, row = idx >> 4, c4 = idx & 15;
                float4 v = *(const float4*)(Vg + (size_t)row * NN + c4 * 4);
                uint2 hi, lo;
                split4(v, hi, lo);
                uint32_t off = (uint32_t)(row * VSTR + c4 * 8);
                *(uint2*)(smem + F_VHI + off) = hi;
                *(uint2*)(smem + F_VLO + off) = lo;
            }
        }
        __syncthreads();

        // ---- S = Q @ Kc^T : warp computes 16 x 64 ----
        float cs[8][4];
        #pragma unroll
        for (int nt = 0; nt < 8; ++nt)
            #pragma unroll
            for (int i = 0; i < 4; ++i) cs[nt][i] = 0.f;

        #pragma unroll
        for (int ks = 0; ks < 8; ++ks) {
            uint32_t ah[4], al[4];
            uint32_t ad = sm + qa_off + (uint32_t)(ks * 32);
            ldmx4(ah[0], ah[1], ah[2], ah[3], ad + F_QHI);
            ldmx4(al[0], al[1], al[2], al[3], ad + F_QLO);
            #pragma unroll
            for (int np = 0; np < 4; ++np) {
                uint32_t bd = sm + kb_base + (uint32_t)(np * 16 * KSTR + ks * 32);
                uint32_t bh[2][2], bl[2][2];
                ldmx4(bh[0][0], bh[0][1], bh[1][0], bh[1][1], bd + F_KHI);
                ldmx4(bl[0][0], bl[0][1], bl[1][0], bl[1][1], bd + F_KLO);
                #pragma unroll
                for (int q = 0; q < 2; ++q) {
                    mma16816(cs[np * 2 + q], ah, bh[q]);
                    mma16816(cs[np * 2 + q], ah, bl[q]);
                    mma16816(cs[np * 2 + q], al, bh[q]);
                }
            }
        }

        // ---- scale + mask bias ----
        #pragma unroll
        for (int nt = 0; nt < 8; ++nt) {
            int col = n0 + nt * 8 + (lane & 3) * 2;
            float mb0 = (1.0f - mask[b * NN + col]) * -1e9f;
            float mb1 = (1.0f - mask[b * NN + col + 1]) * -1e9f;
            cs[nt][0] = cs[nt][0] * SCALE + mb0;
            cs[nt][1] = cs[nt][1] * SCALE + mb1;
            cs[nt][2] = cs[nt][2] * SCALE + mb0;
            cs[nt][3] = cs[nt][3] * SCALE + mb1;
        }

        // ---- online softmax update (rows lane>>2 and +8, 4 lanes/row) ----
        float cm0 = -INFINITY, cm1 = -INFINITY;
        #pragma unroll
        for (int nt = 0; nt < 8; ++nt) {
            cm0 = fmaxf(cm0, fmaxf(cs[nt][0], cs[nt][1]));
            cm1 = fmaxf(cm1, fmaxf(cs[nt][2], cs[nt][3]));
        }
        cm0 = fmaxf(cm0, __shfl_xor_sync(0xFFFFFFFF, cm0, 1));
        cm0 = fmaxf(cm0, __shfl_xor_sync(0xFFFFFFFF, cm0, 2));
        cm1 = fmaxf(cm1, __shfl_xor_sync(0xFFFFFFFF, cm1, 1));
        cm1 = fmaxf(cm1, __shfl_xor_sync(0xFFFFFFFF, cm1, 2));

        float mn0 = fmaxf(m0r, cm0), mn1 = fmaxf(m1r, cm1);
        float f0 = __expf(m0r - mn0), f1 = __expf(m1r - mn1);
        m0r = mn0; m1r = mn1;

        float rs0 = 0.f, rs1 = 0.f;
        #pragma unroll
        for (int nt = 0; nt < 8; ++nt) {
            cs[nt][0] = __expf(cs[nt][0] - mn0);
            cs[nt][1] = __expf(cs[nt][1] - mn0);
            cs[nt][2] = __expf(cs[nt][2] - mn1);
            cs[nt][3] = __expf(cs[nt][3] - mn1);
            rs0 += cs[nt][0] + cs[nt][1];
            rs1 += cs[nt][2] + cs[nt][3];
        }
        rs0 += __shfl_xor_sync(0xFFFFFFFF, rs0, 1);
        rs0 += __shfl_xor_sync(0xFFFFFFFF, rs0, 2);
        rs1 += __shfl_xor_sync(0xFFFFFFFF, rs1, 1);
        rs1 += __shfl_xor_sync(0xFFFFFFFF, rs1, 2);
        l0r = l0r * f0 + rs0;
        l1r = l1r * f1 + rs1;

        // rescale O
        #pragma unroll
        for (int nt = 0; nt < 16; ++nt) {
            co[nt][0] *= f0; co[nt][1] *= f0;
            co[nt][2] *= f1; co[nt][3] *= f1;
        }

        // ---- store P hi/lo to smem ----
        {
            int r0 = lane >> 2;
            uint32_t base0 = (uint32_t)((w * 16 + r0) * VSTR + (lane & 3) * 4);
            #pragma unroll
            for (int nt = 0; nt < 8; ++nt) {
                uint32_t hi, lo;
                split2(cs[nt][0], cs[nt][1], hi, lo);
                uint32_t o0 = base0 + nt * 16;
                *(uint32_t*)(smem + F_PHI + o0) = hi;
                *(uint32_t*)(smem + F_PLO + o0) = lo;
                split2(cs[nt][2], cs[nt][3], hi, lo);
                uint32_t o1 = o0 + 8 * VSTR;
                *(uint32_t*)(smem + F_PHI + o1) = hi;
                *(uint32_t*)(smem + F_PLO + o1) = lo;
            }
        }
        __syncthreads();

        // ---- O += P @ Vc (K-dim = 64) ----
        #pragma unroll
        for (int ks = 0; ks < 4; ++ks) {
            uint32_t ah[4], al[4];
            uint32_t ad = sm + pa_off + (uint32_t)(ks * 32);
            ldmx4(ah[0], ah[1], ah[2], ah[3], ad + F_PHI);
            ldmx4(al[0], al[1], al[2], al[3], ad + F_PLO);
            #pragma unroll
            for (int np = 0; np < 8; ++np) {
                uint32_t bd = sm + vb_base + (uint32_t)(np * 16 * VSTR + ks * 32);
                uint32_t bh[2][2], bl[2][2];
                ldmx4(bh[0][0], bh[0][1], bh[1][0], bh[1][1], bd + F_VHI);
                ldmx4(bl[0][0], bl[0][1], bl[1][0], bl[1][1], bd + F_VLO);
                #pragma unroll
                for (int q = 0; q < 2; ++q) {
                    mma16816(co[np * 2 + q], ah, bh[q]);
                    mma16816(co[np * 2 + q], ah, bl[q]);
                    mma16816(co[np * 2 + q], al, bh[q]);
                }
            }
        }
        __syncthreads();
    }

    // ---- epilogue: normalize and write ctx ----
    float inv0 = 1.0f / l0r, inv1 = 1.0f / l1r;
    int r0 = lane >> 2;
    #pragma unroll
    for (int nt = 0; nt < 16; ++nt) {
        int row = m0 + w * 16 + r0;
        int col = nt * 8 + (lane & 3) * 2;
        float* p0 = g_ctx + (size_t)(b * NN + row) * (HH * HD) + h * HD + col;
        float* p1 = g_ctx + (size_t)(b * NN + row + 8) * (HH * HD) + h * HD + col;
        *(float2*)p0 = make_float2(co[nt][0] * inv0, co[nt][1] * inv0);
        *(float2*)p1 = make_float2(co[nt][2] * inv1, co[nt][3] * inv1);
    }
}

// ---------------------------------------------------------------------------
// Transposes (unchanged)
// ---------------------------------------------------------------------------
__global__ void transpose_f32(const float* __restrict__ src, float* __restrict__ dst,
                              int R, int C)
{
    __shared__ float tile[32][33];
    int c0 = blockIdx.x * 32, r0 = blockIdx.y * 32;
    int tx = threadIdx.x, ty = threadIdx.y;
    #pragma unroll
    for (int i = ty; i < 32; i += 8)
        tile[i][tx] = src[(size_t)(r0 + i) * C + c0 + tx];
    __syncthreads();
    #pragma unroll
    for (int i = ty; i < 32; i += 8)
        dst[(size_t)(c0 + i) * R + r0 + tx] = tile[tx][i];
}

__global__ void transpose_v(const float* __restrict__ qkv)
{
    __shared__ float tile[32][33];
    int z = blockIdx.z, b = z / HKV, hkv = z % HKV;
    int n0 = blockIdx.x * 32, d0 = blockIdx.y * 32;
    int tx = threadIdx.x, ty = threadIdx.y;
    #pragma unroll
    for (int i = ty; i < 32; i += 8)
        tile[i][tx] = qkv[(size_t)(b * NN + n0 + i) * QKVW + VOFF + hkv * HD + d0 + tx];
    __syncthreads();
    float* dst = g_Vt + (size_t)(b * HKV + hkv) * HD * NN;
    #pragma unroll
    for (int i = ty; i < 32; i += 8)
        dst[(size_t)(d0 + i) * NN + n0 + tx] = tile[tx][i];
}

// ---------------------------------------------------------------------------
// RoPE (unchanged)
// ---------------------------------------------------------------------------
__global__ void rope_kernel(const float* __restrict__ cosb,
                            const float* __restrict__ sinb,
                            float* __restrict__ qkv)
{
    int idx = blockIdx.x * blockDim.x + threadIdx.x;
    const int NQ = BB * NN * HH * (HD / 2);
    const int NK = BB * NN * HKV * (HD / 2);
    if (idx < NQ) {
        int i  = idx & 63;
        int h  = (idx >> 6) % HH;
        int bn = idx / (64 * HH);
        int n  = bn % NN;
        float c = cosb[n * 64 + i], s = sinb[n * 64 + i];
        float* q = qkv + (size_t)bn * QKVW + h * HD;
        float t1 = q[i], t2 = q[i + 64];
        q[i]      = t1 * c + t2 * s;
        q[i + 64] = t2 * c - t1 * s;
    } else {
        idx -= NQ;
        if (idx < NK) {
            int i  = idx & 63;
            int hk = (idx >> 6) % HKV;
            int bn = idx / (64 * HKV);
            int n  = bn % NN;
            float c = cosb[n * 64 + i], s = sinb[n * 64 + i];
            float* k = qkv + (size_t)bn * QKVW + KOFF + hk * HD;
            float t1 = k[i], t2 = k[i + 64];
            k[i]      = t1 * c + t2 * s;
            k[i + 64] = t2 * c - t1 * s;
        }
    }
}

// ---------------------------------------------------------------------------
// Launch
// ---------------------------------------------------------------------------
extern "C" void kernel_launch(void* const* d_in, const int* in_sizes, int n_in,
                              void* d_out, int out_size)
{
    (void)in_sizes; (void)n_in; (void)out_size;

    const float* x    = (const float*)d_in[0];
    const float* cosb = (const float*)d_in[1];
    const float* sinb = (const float*)d_in[2];
    const float* mask = (const float*)d_in[3];
    const float* Wq   = (const float*)d_in[4];
    const float* Wkv  = (const float*)d_in[5];
    const float* Wo   = (const float*)d_in[6];
    const float* bo   = (const float*)d_in[7];
    float* out = (float*)d_out;

    float *pQKV, *pWT, *pWoT, *pCtx;
    cudaGetSymbolAddress((void**)&pQKV, g_QKV);
    cudaGetSymbolAddress((void**)&pWT,  g_WT);
    cudaGetSymbolAddress((void**)&pWoT, g_WoT);
    cudaGetSymbolAddress((void**)&pCtx, g_ctx);

    cudaFuncSetAttribute(gemm_nt_mma, cudaFuncAttributeMaxDynamicSharedMemorySize, SMEM_SZ);
    cudaFuncSetAttribute(flash_attn,  cudaFuncAttributeMaxDynamicSharedMemorySize, F_SZ);

    const int M = BB * NN;   // 4096
    dim3 tb(32, 8);

    // Weight transposes
    transpose_f32<<<dim3(DD / 32, DD / 32), tb>>>(Wq, pWT, DD, DD);
    transpose_f32<<<dim3((2 * HKV * HD) / 32, DD / 32), tb>>>(Wkv, pWT + (size_t)KOFF * DD, DD, 2 * HKV * HD);
    transpose_f32<<<dim3(DD / 32, DD / 32), tb>>>(Wo, pWoT, DD, DD);

    // QKV = x @ [Wq|Wkv]
    gemm_nt_mma<<<dim3(QKVW / 128, M / 128), 256, SMEM_SZ>>>(x, DD, pWT, DD, pQKV, QKVW, DD, nullptr);

    // RoPE
    {
        int total = BB * NN * HH * (HD / 2) + BB * NN * HKV * (HD / 2);
        rope_kernel<<<(total + 255) / 256, 256>>>(cosb, sinb, pQKV);
    }

    // V transpose
    transpose_v<<<dim3(NN / 32, HD / 32, BB * HKV), tb>>>(pQKV);

    // fused attention: scores + softmax + PV
    flash_attn<<<dim3(1, NN / 128, BB * HH), 256, F_SZ>>>(mask, pQKV);

    // out = ctx @ Wo + bo
    gemm_nt_mma<<<dim3(DD / 128, M / 128), 256, SMEM_SZ>>>(pCtx, HH * HD, pWoT, DD, out, DD, DD, bo);
}

// round 8
// speedup vs baseline: 1.8145x; 1.0663x over previous
#include <cuda_runtime.h>
#include <cuda_bf16.h>
#include <math.h>
#include <cstdint>

// ---------------------------------------------------------------------------
// Problem constants
// ---------------------------------------------------------------------------
#define BB   2
#define NN   2048
#define DD   2048
#define HH   16
#define HKV  4
#define HD   128
#define GG   (HH / HKV)
#define QKVW (HH * HD + 2 * HKV * HD)     // 3072: Q(2048) | K(512) | V(512)
#define KOFF (HH * HD)                    // 2048
#define VOFF (HH * HD + HKV * HD)         // 2560
#define SCALE 0.08838834764831845f

#define BK 32                  // K-chunk (fp32 elements) for gemm
#define TSTR 80                // gemm smem row stride bytes (64 data + 16 pad)
#define TILE_B (128 * TSTR)
#define STAGE_B (4 * TILE_B)
#define SMEM_SZ (2 * STAGE_B)  // 81920 (gemm)
#define OFF_AHI 0
#define OFF_ALO (TILE_B)
#define OFF_BHI (2 * TILE_B)
#define OFF_BLO (3 * TILE_B)

// flash-attention smem layout (bytes)
#define KSTR 272               // 128 bf16 cols (256B) + 16 pad
#define VSTR 144               // 64 bf16 cols (128B) + 16 pad
#define F_QHI 0
#define F_QLO (F_QHI + 128 * KSTR)
#define F_KHI (F_QLO + 128 * KSTR)
#define F_KLO (F_KHI + 64 * KSTR)
#define F_VHI (F_KLO + 64 * KSTR)
#define F_VLO (F_VHI + 128 * VSTR)
#define F_PHI (F_VLO + 128 * VSTR)
#define F_PLO (F_PHI + 128 * VSTR)
#define F_SZ  (F_PLO + 128 * VSTR)    // 178176

// ---------------------------------------------------------------------------
// Device scratch
// ---------------------------------------------------------------------------
__device__ float g_QKV[(size_t)BB * NN * QKVW];            // 48 MB
__device__ float g_WT [(size_t)QKVW * DD];                 // 24 MB
__device__ float g_WoT[(size_t)DD * DD];                   // 16 MB
__device__ float g_Vt [(size_t)BB * HKV * HD * NN];        // 8 MB  [b][hkv][hd][n]
__device__ float g_ctx[(size_t)BB * NN * HH * HD];         // 32 MB

// ---------------------------------------------------------------------------
// PTX helpers
// ---------------------------------------------------------------------------
__device__ __forceinline__ uint32_t smem_u32(const void* p) {
    uint32_t a;
    asm("{ .reg .u64 t; cvta.to.shared.u64 t, %1; cvt.u32.u64 %0, t; }" : "=r"(a) : "l"(p));
    return a;
}
__device__ __forceinline__ void ldmx4(uint32_t& r0, uint32_t& r1, uint32_t& r2, uint32_t& r3, uint32_t addr) {
    asm volatile("ldmatrix.sync.aligned.m8n8.x4.shared.b16 {%0,%1,%2,%3}, [%4];"
                 : "=r"(r0), "=r"(r1), "=r"(r2), "=r"(r3) : "r"(addr));
}
__device__ __forceinline__ void mma16816(float* c, const uint32_t* a, const uint32_t* b) {
    asm volatile(
        "mma.sync.aligned.m16n8k16.row.col.f32.bf16.bf16.f32 "
        "{%0,%1,%2,%3}, {%4,%5,%6,%7}, {%8,%9}, {%0,%1,%2,%3};"
        : "+f"(c[0]), "+f"(c[1]), "+f"(c[2]), "+f"(c[3])
        : "r"(a[0]), "r"(a[1]), "r"(a[2]), "r"(a[3]), "r"(b[0]), "r"(b[1]));
}

__device__ __forceinline__ void split4(float4 v, uint2& hi, uint2& lo) {
    __nv_bfloat16 hx = __float2bfloat16(v.x), hy = __float2bfloat16(v.y),
                  hz = __float2bfloat16(v.z), hw = __float2bfloat16(v.w);
    __nv_bfloat162 h01 = __halves2bfloat162(hx, hy), h23 = __halves2bfloat162(hz, hw);
    __nv_bfloat16 lx = __float2bfloat16(v.x - __bfloat162float(hx));
    __nv_bfloat16 ly = __float2bfloat16(v.y - __bfloat162float(hy));
    __nv_bfloat16 lz = __float2bfloat16(v.z - __bfloat162float(hz));
    __nv_bfloat16 lw = __float2bfloat16(v.w - __bfloat162float(hw));
    __nv_bfloat162 l01 = __halves2bfloat162(lx, ly), l23 = __halves2bfloat162(lz, lw);
    hi = make_uint2(*(uint32_t*)&h01, *(uint32_t*)&h23);
    lo = make_uint2(*(uint32_t*)&l01, *(uint32_t*)&l23);
}
__device__ __forceinline__ void split2(float a, float b, uint32_t& hi, uint32_t& lo) {
    __nv_bfloat16 ha = __float2bfloat16(a), hb = __float2bfloat16(b);
    __nv_bfloat16 la = __float2bfloat16(a - __bfloat162float(ha));
    __nv_bfloat16 lb = __float2bfloat16(b - __bfloat162float(hb));
    __nv_bfloat162 hp = __halves2bfloat162(ha, hb), lp = __halves2bfloat162(la, lb);
    hi = *(uint32_t*)&hp; lo = *(uint32_t*)&lp;
}

// gemm stage store — 512-thread version (2 iterations)
__device__ __forceinline__ void store_stage(char* sb, int t, const float4* pa, const float4* pb) {
    #pragma unroll
    for (int i = 0; i < 2; ++i) {
        int idx = t + i * 512, row = idx >> 3, c4 = idx & 7;
        uint32_t off = (uint32_t)(row * TSTR + c4 * 8);
        uint2 hi, lo;
        split4(pa[i], hi, lo);
        *(uint2*)(sb + OFF_AHI + off) = hi;
        *(uint2*)(sb + OFF_ALO + off) = lo;
        split4(pb[i], hi, lo);
        *(uint2*)(sb + OFF_BHI + off) = hi;
        *(uint2*)(sb + OFF_BLO + off) = lo;
    }
}

// ---------------------------------------------------------------------------
// GEMM mainloop — 512 threads, 16 warps (4M x 4N), warp tile 32x32.
// Double-buffered smem, one __syncthreads per chunk; next-chunk LDG issued
// before the MMA phase so global latency hides under tensor work.
// ---------------------------------------------------------------------------
__device__ __forceinline__ void mma_mainloop(
    const float* __restrict__ A, int lda,
    const float* __restrict__ B, int ldb, int K,
    float c[2][4][4])
{
    extern __shared__ __align__(16) char smem[];
    const int t    = threadIdx.x;
    const int lane = t & 31;
    const int warp = t >> 5;
    const int wm   = warp >> 2;   // 0..3 (M)
    const int wn   = warp & 3;    // 0..3 (N)
    const uint32_t sm = smem_u32(smem);

    const uint32_t a_off = (uint32_t)((wm * 32 + (lane & 15)) * TSTR + (lane >> 4) * 16);
    const uint32_t b_off = (uint32_t)(OFF_BHI + (wn * 32 + ((lane >> 4) * 8) + (lane & 7)) * TSTR + ((lane >> 3) & 1) * 16);

    float4 pa[2], pb[2];
    const int nch = K / BK;

    #pragma unroll
    for (int i = 0; i < 2; ++i) {
        int idx = t + i * 512, row = idx >> 3, c4 = idx & 7;
        pa[i] = *(const float4*)(A + (size_t)row * lda + c4 * 4);
        pb[i] = *(const float4*)(B + (size_t)row * ldb + c4 * 4);
    }
    store_stage(smem, t, pa, pb);
    __syncthreads();

    uint32_t buf = 0;
    for (int ch = 0; ch < nch; ++ch) {
        if (ch + 1 < nch) {
            const int k0 = (ch + 1) * BK;
            #pragma unroll
            for (int i = 0; i < 2; ++i) {
                int idx = t + i * 512, row = idx >> 3, c4 = idx & 7;
                pa[i] = *(const float4*)(A + (size_t)row * lda + k0 + c4 * 4);
                pb[i] = *(const float4*)(B + (size_t)row * ldb + k0 + c4 * 4);
            }
        }
        const uint32_t sb = sm + buf * STAGE_B;
        #pragma unroll
        for (int ks = 0; ks < 2; ++ks) {
            uint32_t ah[2][4], al[2][4], bh[4][2], bl[4][2];
            #pragma unroll
            for (int mt = 0; mt < 2; ++mt) {
                uint32_t ad = sb + a_off + (uint32_t)(mt * 16 * TSTR + ks * 32);
                ldmx4(ah[mt][0], ah[mt][1], ah[mt][2], ah[mt][3], ad + OFF_AHI);
                ldmx4(al[mt][0], al[mt][1], al[mt][2], al[mt][3], ad + OFF_ALO);
            }
            #pragma unroll
            for (int np = 0; np < 2; ++np) {
                uint32_t ad = sb + b_off + (uint32_t)(np * 16 * TSTR + ks * 32);
                ldmx4(bh[np * 2][0], bh[np * 2][1], bh[np * 2 + 1][0], bh[np * 2 + 1][1], ad);
                ldmx4(bl[np * 2][0], bl[np * 2][1], bl[np * 2 + 1][0], bl[np * 2 + 1][1], ad + TILE_B);
            }
            #pragma unroll
            for (int mt = 0; mt < 2; ++mt)
                #pragma unroll
                for (int nt = 0; nt < 4; ++nt) {
                    mma16816(c[mt][nt], ah[mt], bh[nt]);
                    mma16816(c[mt][nt], ah[mt], bl[nt]);
                    mma16816(c[mt][nt], al[mt], bh[nt]);
                }
        }
        if (ch + 1 < nch)
            store_stage(smem + (buf ^ 1) * STAGE_B, t, pa, pb);
        __syncthreads();
        buf ^= 1;
    }
}

#define ACC_INIT4(c) \
    _Pragma("unroll") for (int mt = 0; mt < 2; ++mt) \
    _Pragma("unroll") for (int nt = 0; nt < 4; ++nt) \
    _Pragma("unroll") for (int i = 0; i < 4; ++i) c[mt][nt][i] = 0.f

// ---------------------------------------------------------------------------
// Generic NT GEMM: C[m0+i][n0+j] = sum_k A[m0+i][k]*B[n0+j][k] (+bias)
// 512 threads.
// ---------------------------------------------------------------------------
__global__ __launch_bounds__(512) void gemm_nt_mma(
    const float* __restrict__ A, int lda,
    const float* __restrict__ B, int ldb,
    float* __restrict__ C, int ldc, int K,
    const float* __restrict__ bias)
{
    const int m0 = blockIdx.y * 128, n0 = blockIdx.x * 128;
    float c[2][4][4];
    ACC_INIT4(c);

    mma_mainloop(A + (size_t)m0 * lda, lda, B + (size_t)n0 * ldb, ldb, K, c);

    const int lane = threadIdx.x & 31, warp = threadIdx.x >> 5;
    const int rb = m0 + (warp >> 2) * 32 + (lane >> 2);
    const int cb = n0 + (warp & 3) * 32 + (lane & 3) * 2;
    #pragma unroll
    for (int mt = 0; mt < 2; ++mt)
        #pragma unroll
        for (int nt = 0; nt < 4; ++nt) {
            int row = rb + mt * 16, col = cb + nt * 8;
            float b0 = bias ? bias[col] : 0.f, b1 = bias ? bias[col + 1] : 0.f;
            *(float2*)(C + (size_t)row * ldc + col)       = make_float2(c[mt][nt][0] + b0, c[mt][nt][1] + b1);
            *(float2*)(C + (size_t)(row + 8) * ldc + col) = make_float2(c[mt][nt][2] + b0, c[mt][nt][3] + b1);
        }
}

// ---------------------------------------------------------------------------
// Fused flash attention (unchanged from R7): per CTA = (b,h) x 128 q-rows,
// 256 threads, online softmax, 3-MMA hi/lo QK and PV.
// ---------------------------------------------------------------------------
__global__ __launch_bounds__(256) void flash_attn(
    const float* __restrict__ mask, const float* __restrict__ qkv)
{
    extern __shared__ __align__(16) char smem[];
    const int z = blockIdx.z, b = z / HH, h = z % HH, hkv = h % HKV;
    const int m0 = blockIdx.y * 128;
    const int t = threadIdx.x, lane = t & 31, w = t >> 5;
    const uint32_t sm = smem_u32(smem);

    {
        const float* Qg = qkv + (size_t)(b * NN + m0) * QKVW + h * HD;
        #pragma unroll
        for (int i = 0; i < 16; ++i) {
            int idx = t + i * 256, row = idx >> 5, c4 = idx & 31;
            float4 v = *(const float4*)(Qg + (size_t)row * QKVW + c4 * 4);
            uint2 hi, lo;
            split4(v, hi, lo);
            uint32_t off = (uint32_t)(row * KSTR + c4 * 8);
            *(uint2*)(smem + F_QHI + off) = hi;
            *(uint2*)(smem + F_QLO + off) = lo;
        }
    }

    float co[16][4];
    #pragma unroll
    for (int nt = 0; nt < 16; ++nt)
        #pragma unroll
        for (int i = 0; i < 4; ++i) co[nt][i] = 0.f;
    float m0r = -INFINITY, m1r = -INFINITY;
    float l0r = 0.f, l1r = 0.f;

    const uint32_t qa_off = (uint32_t)((w * 16 + (lane & 15)) * KSTR + (lane >> 4) * 16);
    const uint32_t kb_base = (uint32_t)(((lane >> 4) * 8 + (lane & 7)) * KSTR + ((lane >> 3) & 1) * 16);
    const uint32_t pa_off = (uint32_t)((w * 16 + (lane & 15)) * VSTR + (lane >> 4) * 16);
    const uint32_t vb_base = (uint32_t)(((lane >> 4) * 8 + (lane & 7)) * VSTR + ((lane >> 3) & 1) * 16);

    __syncthreads();

    for (int ch = 0; ch < NN / 64; ++ch) {
        const int n0 = ch * 64;
        {
            const float* Kg = qkv + (size_t)(b * NN + n0) * QKVW + KOFF + hkv * HD;
            #pragma unroll
            for (int i = 0; i < 8; ++i) {
                int idx = t + i * 256, row = idx >> 5, c4 = idx & 31;
                float4 v = *(const float4*)(Kg + (size_t)row * QKVW + c4 * 4);
                uint2 hi, lo;
                split4(v, hi, lo);
                uint32_t off = (uint32_t)(row * KSTR + c4 * 8);
                *(uint2*)(smem + F_KHI + off) = hi;
                *(uint2*)(smem + F_KLO + off) = lo;
            }
        }
        {
            const float* Vg = g_Vt + (size_t)(b * HKV + hkv) * HD * NN + n0;
            #pragma unroll
            for (int i = 0; i < 8; ++i) {
                int idx = t + i * 256, row = idx >> 4, c4 = idx & 15;
                float4 v = *(const float4*)(Vg + (size_t)row * NN + c4 * 4);
                uint2 hi, lo;
                split4(v, hi, lo);
                uint32_t off = (uint32_t)(row * VSTR + c4 * 8);
                *(uint2*)(smem + F_VHI + off) = hi;
                *(uint2*)(smem + F_VLO + off) = lo;
            }
        }
        __syncthreads();

        float cs[8][4];
        #pragma unroll
        for (int nt = 0; nt < 8; ++nt)
            #pragma unroll
            for (int i = 0; i < 4; ++i) cs[nt][i] = 0.f;

        #pragma unroll
        for (int ks = 0; ks < 8; ++ks) {
            uint32_t ah[4], al[4];
            uint32_t ad = sm + qa_off + (uint32_t)(ks * 32);
            ldmx4(ah[0], ah[1], ah[2], ah[3], ad + F_QHI);
            ldmx4(al[0], al[1], al[2], al[3], ad + F_QLO);
            #pragma unroll
            for (int np = 0; np < 4; ++np) {
                uint32_t bd = sm + kb_base + (uint32_t)(np * 16 * KSTR + ks * 32);
                uint32_t bh[2][2], bl[2][2];
                ldmx4(bh[0][0], bh[0][1], bh[1][0], bh[1][1], bd + F_KHI);
                ldmx4(bl[0][0], bl[0][1], bl[1][0], bl[1][1], bd + F_KLO);
                #pragma unroll
                for (int q = 0; q < 2; ++q) {
                    mma16816(cs[np * 2 + q], ah, bh[q]);
                    mma16816(cs[np * 2 + q], ah, bl[q]);
                    mma16816(cs[np * 2 + q], al, bh[q]);
                }
            }
        }

        #pragma unroll
        for (int nt = 0; nt < 8; ++nt) {
            int col = n0 + nt * 8 + (lane & 3) * 2;
            float mb0 = (1.0f - mask[b * NN + col]) * -1e9f;
            float mb1 = (1.0f - mask[b * NN + col + 1]) * -1e9f;
            cs[nt][0] = cs[nt][0] * SCALE + mb0;
            cs[nt][1] = cs[nt][1] * SCALE + mb1;
            cs[nt][2] = cs[nt][2] * SCALE + mb0;
            cs[nt][3] = cs[nt][3] * SCALE + mb1;
        }

        float cm0 = -INFINITY, cm1 = -INFINITY;
        #pragma unroll
        for (int nt = 0; nt < 8; ++nt) {
            cm0 = fmaxf(cm0, fmaxf(cs[nt][0], cs[nt][1]));
            cm1 = fmaxf(cm1, fmaxf(cs[nt][2], cs[nt][3]));
        }
        cm0 = fmaxf(cm0, __shfl_xor_sync(0xFFFFFFFF, cm0, 1));
        cm0 = fmaxf(cm0, __shfl_xor_sync(0xFFFFFFFF, cm0, 2));
        cm1 = fmaxf(cm1, __shfl_xor_sync(0xFFFFFFFF, cm1, 1));
        cm1 = fmaxf(cm1, __shfl_xor_sync(0xFFFFFFFF, cm1, 2));

        float mn0 = fmaxf(m0r, cm0), mn1 = fmaxf(m1r, cm1);
        float f0 = __expf(m0r - mn0), f1 = __expf(m1r - mn1);
        m0r = mn0; m1r = mn1;

        float rs0 = 0.f, rs1 = 0.f;
        #pragma unroll
        for (int nt = 0; nt < 8; ++nt) {
            cs[nt][0] = __expf(cs[nt][0] - mn0);
            cs[nt][1] = __expf(cs[nt][1] - mn0);
            cs[nt][2] = __expf(cs[nt][2] - mn1);
            cs[nt][3] = __expf(cs[nt][3] - mn1);
            rs0 += cs[nt][0] + cs[nt][1];
            rs1 += cs[nt][2] + cs[nt][3];
        }
        rs0 += __shfl_xor_sync(0xFFFFFFFF, rs0, 1);
        rs0 += __shfl_xor_sync(0xFFFFFFFF, rs0, 2);
        rs1 += __shfl_xor_sync(0xFFFFFFFF, rs1, 1);
        rs1 += __shfl_xor_sync(0xFFFFFFFF, rs1, 2);
        l0r = l0r * f0 + rs0;
        l1r = l1r * f1 + rs1;

        #pragma unroll
        for (int nt = 0; nt < 16; ++nt) {
            co[nt][0] *= f0; co[nt][1] *= f0;
            co[nt][2] *= f1; co[nt][3] *= f1;
        }

        {
            int r0 = lane >> 2;
            uint32_t base0 = (uint32_t)((w * 16 + r0) * VSTR + (lane & 3) * 4);
            #pragma unroll
            for (int nt = 0; nt < 8; ++nt) {
                uint32_t hi, lo;
                split2(cs[nt][0], cs[nt][1], hi, lo);
                uint32_t o0 = base0 + nt * 16;
                *(uint32_t*)(smem + F_PHI + o0) = hi;
                *(uint32_t*)(smem + F_PLO + o0) = lo;
                split2(cs[nt][2], cs[nt][3], hi, lo);
                uint32_t o1 = o0 + 8 * VSTR;
                *(uint32_t*)(smem + F_PHI + o1) = hi;
                *(uint32_t*)(smem + F_PLO + o1) = lo;
            }
        }
        __syncthreads();

        #pragma unroll
        for (int ks = 0; ks < 4; ++ks) {
            uint32_t ah[4], al[4];
            uint32_t ad = sm + pa_off + (uint32_t)(ks * 32);
            ldmx4(ah[0], ah[1], ah[2], ah[3], ad + F_PHI);
            ldmx4(al[0], al[1], al[2], al[3], ad + F_PLO);
            #pragma unroll
            for (int np = 0; np < 8; ++np) {
                uint32_t bd = sm + vb_base + (uint32_t)(np * 16 * VSTR + ks * 32);
                uint32_t bh[2][2], bl[2][2];
                ldmx4(bh[0][0], bh[0][1], bh[1][0], bh[1][1], bd + F_VHI);
                ldmx4(bl[0][0], bl[0][1], bl[1][0], bl[1][1], bd + F_VLO);
                #pragma unroll
                for (int q = 0; q < 2; ++q) {
                    mma16816(co[np * 2 + q], ah, bh[q]);
                    mma16816(co[np * 2 + q], ah, bl[q]);
                    mma16816(co[np * 2 + q], al, bh[q]);
                }
            }
        }
        __syncthreads();
    }

    float inv0 = 1.0f / l0r, inv1 = 1.0f / l1r;
    int r0 = lane >> 2;
    #pragma unroll
    for (int nt = 0; nt < 16; ++nt) {
        int row = m0 + w * 16 + r0;
        int col = nt * 8 + (lane & 3) * 2;
        float* p0 = g_ctx + (size_t)(b * NN + row) * (HH * HD) + h * HD + col;
        float* p1 = g_ctx + (size_t)(b * NN + row + 8) * (HH * HD) + h * HD + col;
        *(float2*)p0 = make_float2(co[nt][0] * inv0, co[nt][1] * inv0);
        *(float2*)p1 = make_float2(co[nt][2] * inv1, co[nt][3] * inv1);
    }
}

// ---------------------------------------------------------------------------
// Transposes (unchanged)
// ---------------------------------------------------------------------------
__global__ void transpose_f32(const float* __restrict__ src, float* __restrict__ dst,
                              int R, int C)
{
    __shared__ float tile[32][33];
    int c0 = blockIdx.x * 32, r0 = blockIdx.y * 32;
    int tx = threadIdx.x, ty = threadIdx.y;
    #pragma unroll
    for (int i = ty; i < 32; i += 8)
        tile[i][tx] = src[(size_t)(r0 + i) * C + c0 + tx];
    __syncthreads();
    #pragma unroll
    for (int i = ty; i < 32; i += 8)
        dst[(size_t)(c0 + i) * R + r0 + tx] = tile[tx][i];
}

__global__ void transpose_v(const float* __restrict__ qkv)
{
    __shared__ float tile[32][33];
    int z = blockIdx.z, b = z / HKV, hkv = z % HKV;
    int n0 = blockIdx.x * 32, d0 = blockIdx.y * 32;
    int tx = threadIdx.x, ty = threadIdx.y;
    #pragma unroll
    for (int i = ty; i < 32; i += 8)
        tile[i][tx] = qkv[(size_t)(b * NN + n0 + i) * QKVW + VOFF + hkv * HD + d0 + tx];
    __syncthreads();
    float* dst = g_Vt + (size_t)(b * HKV + hkv) * HD * NN;
    #pragma unroll
    for (int i = ty; i < 32; i += 8)
        dst[(size_t)(d0 + i) * NN + n0 + tx] = tile[tx][i];
}

// ---------------------------------------------------------------------------
// RoPE (unchanged)
// ---------------------------------------------------------------------------
__global__ void rope_kernel(const float* __restrict__ cosb,
                            const float* __restrict__ sinb,
                            float* __restrict__ qkv)
{
    int idx = blockIdx.x * blockDim.x + threadIdx.x;
    const int NQ = BB * NN * HH * (HD / 2);
    const int NK = BB * NN * HKV * (HD / 2);
    if (idx < NQ) {
        int i  = idx & 63;
        int h  = (idx >> 6) % HH;
        int bn = idx / (64 * HH);
        int n  = bn % NN;
        float c = cosb[n * 64 + i], s = sinb[n * 64 + i];
        float* q = qkv + (size_t)bn * QKVW + h * HD;
        float t1 = q[i], t2 = q[i + 64];
        q[i]      = t1 * c + t2 * s;
        q[i + 64] = t2 * c - t1 * s;
    } else {
        idx -= NQ;
        if (idx < NK) {
            int i  = idx & 63;
            int hk = (idx >> 6) % HKV;
            int bn = idx / (64 * HKV);
            int n  = bn % NN;
            float c = cosb[n * 64 + i], s = sinb[n * 64 + i];
            float* k = qkv + (size_t)bn * QKVW + KOFF + hk * HD;
            float t1 = k[i], t2 = k[i + 64];
            k[i]      = t1 * c + t2 * s;
            k[i + 64] = t2 * c - t1 * s;
        }
    }
}

// ---------------------------------------------------------------------------
// Launch
// ---------------------------------------------------------------------------
extern "C" void kernel_launch(void* const* d_in, const int* in_sizes, int n_in,
                              void* d_out, int out_size)
{
    (void)in_sizes; (void)n_in; (void)out_size;

    const float* x    = (const float*)d_in[0];
    const float* cosb = (const float*)d_in[1];
    const float* sinb = (const float*)d_in[2];
    const float* mask = (const float*)d_in[3];
    const float* Wq   = (const float*)d_in[4];
    const float* Wkv  = (const float*)d_in[5];
    const float* Wo   = (const float*)d_in[6];
    const float* bo   = (const float*)d_in[7];
    float* out = (float*)d_out;

    float *pQKV, *pWT, *pWoT, *pCtx;
    cudaGetSymbolAddress((void**)&pQKV, g_QKV);
    cudaGetSymbolAddress((void**)&pWT,  g_WT);
    cudaGetSymbolAddress((void**)&pWoT, g_WoT);
    cudaGetSymbolAddress((void**)&pCtx, g_ctx);

    cudaFuncSetAttribute(gemm_nt_mma, cudaFuncAttributeMaxDynamicSharedMemorySize, SMEM_SZ);
    cudaFuncSetAttribute(flash_attn,  cudaFuncAttributeMaxDynamicSharedMemorySize, F_SZ);

    const int M = BB * NN;   // 4096
    dim3 tb(32, 8);

    // Weight transposes
    transpose_f32<<<dim3(DD / 32, DD / 32), tb>>>(Wq, pWT, DD, DD);
    transpose_f32<<<dim3((2 * HKV * HD) / 32, DD / 32), tb>>>(Wkv, pWT + (size_t)KOFF * DD, DD, 2 * HKV * HD);
    transpose_f32<<<dim3(DD / 32, DD / 32), tb>>>(Wo, pWoT, DD, DD);

    // QKV = x @ [Wq|Wkv]
    gemm_nt_mma<<<dim3(QKVW / 128, M / 128), 512, SMEM_SZ>>>(x, DD, pWT, DD, pQKV, QKVW, DD, nullptr);

    // RoPE
    {
        int total = BB * NN * HH * (HD / 2) + BB * NN * HKV * (HD / 2);
        rope_kernel<<<(total + 255) / 256, 256>>>(cosb, sinb, pQKV);
    }

    // V transpose
    transpose_v<<<dim3(NN / 32, HD / 32, BB * HKV), tb>>>(pQKV);

    // fused attention: scores + softmax + PV
    flash_attn<<<dim3(1, NN / 128, BB * HH), 256, F_SZ>>>(mask, pQKV);

    // out = ctx @ Wo + bo
    gemm_nt_mma<<<dim3(DD / 128, M / 128), 512, SMEM_SZ>>>(pCtx, HH * HD, pWoT, DD, out, DD, DD, bo);
}

// round 9
// speedup vs baseline: 1.8492x; 1.0191x over previous
#include <cuda_runtime.h>
#include <cuda_bf16.h>
#include <math.h>
#include <cstdint>

// ---------------------------------------------------------------------------
// Problem constants
// ---------------------------------------------------------------------------
#define BB   2
#define NN   2048
#define DD   2048
#define HH   16
#define HKV  4
#define HD   128
#define GG   (HH / HKV)
#define QKVW (HH * HD + 2 * HKV * HD)     // 3072: Q(2048) | K(512) | V(512)
#define KOFF (HH * HD)                    // 2048
#define VOFF (HH * HD + HKV * HD)         // 2560
#define SCALE 0.08838834764831845f

#define BK 32                  // K-chunk (fp32 elements) for gemm
#define TSTR 80                // gemm smem row stride bytes (64 data + 16 pad)
#define TILE_B (128 * TSTR)
#define STAGE_B (4 * TILE_B)
#define SMEM_SZ (2 * STAGE_B)  // 81920 (gemm)
#define OFF_AHI 0
#define OFF_ALO (TILE_B)
#define OFF_BHI (2 * TILE_B)
#define OFF_BLO (3 * TILE_B)

// flash-attention smem layout (bytes)
#define KSTR 272               // 128 bf16 cols (256B) + 16 pad
#define VSTR 144               // 64 bf16 cols (128B) + 16 pad
#define F_QHI 0
#define F_QLO (F_QHI + 128 * KSTR)
#define F_KHI (F_QLO + 128 * KSTR)
#define F_KLO (F_KHI + 64 * KSTR)
#define F_VHI (F_KLO + 64 * KSTR)
#define F_VLO (F_VHI + 128 * VSTR)
#define F_PHI (F_VLO + 128 * VSTR)
#define F_PLO (F_PHI + 128 * VSTR)
#define F_SZ  (F_PLO + 128 * VSTR)    // 178176

// ---------------------------------------------------------------------------
// Device scratch
// ---------------------------------------------------------------------------
__device__ float g_QKV[(size_t)BB * NN * QKVW];            // 48 MB
__device__ float g_WT [(size_t)QKVW * DD];                 // 24 MB
__device__ float g_WoT[(size_t)DD * DD];                   // 16 MB
__device__ float g_ctx[(size_t)BB * NN * HH * HD];         // 32 MB

// pre-split bf16 hi/lo attention operands
__device__ __align__(128) __nv_bfloat16 g_Qh [(size_t)BB * NN * HH * HD];
__device__ __align__(128) __nv_bfloat16 g_Ql [(size_t)BB * NN * HH * HD];
__device__ __align__(128) __nv_bfloat16 g_Kh [(size_t)BB * NN * HKV * HD];
__device__ __align__(128) __nv_bfloat16 g_Kl [(size_t)BB * NN * HKV * HD];
__device__ __align__(128) __nv_bfloat16 g_Vth[(size_t)BB * HKV * HD * NN];
__device__ __align__(128) __nv_bfloat16 g_Vtl[(size_t)BB * HKV * HD * NN];

// ---------------------------------------------------------------------------
// PTX helpers
// ---------------------------------------------------------------------------
__device__ __forceinline__ uint32_t smem_u32(const void* p) {
    uint32_t a;
    asm("{ .reg .u64 t; cvta.to.shared.u64 t, %1; cvt.u32.u64 %0, t; }" : "=r"(a) : "l"(p));
    return a;
}
__device__ __forceinline__ void ldmx4(uint32_t& r0, uint32_t& r1, uint32_t& r2, uint32_t& r3, uint32_t addr) {
    asm volatile("ldmatrix.sync.aligned.m8n8.x4.shared.b16 {%0,%1,%2,%3}, [%4];"
                 : "=r"(r0), "=r"(r1), "=r"(r2), "=r"(r3) : "r"(addr));
}
__device__ __forceinline__ void mma16816(float* c, const uint32_t* a, const uint32_t* b) {
    asm volatile(
        "mma.sync.aligned.m16n8k16.row.col.f32.bf16.bf16.f32 "
        "{%0,%1,%2,%3}, {%4,%5,%6,%7}, {%8,%9}, {%0,%1,%2,%3};"
        : "+f"(c[0]), "+f"(c[1]), "+f"(c[2]), "+f"(c[3])
        : "r"(a[0]), "r"(a[1]), "r"(a[2]), "r"(a[3]), "r"(b[0]), "r"(b[1]));
}

__device__ __forceinline__ void split4(float4 v, uint2& hi, uint2& lo) {
    __nv_bfloat16 hx = __float2bfloat16(v.x), hy = __float2bfloat16(v.y),
                  hz = __float2bfloat16(v.z), hw = __float2bfloat16(v.w);
    __nv_bfloat162 h01 = __halves2bfloat162(hx, hy), h23 = __halves2bfloat162(hz, hw);
    __nv_bfloat16 lx = __float2bfloat16(v.x - __bfloat162float(hx));
    __nv_bfloat16 ly = __float2bfloat16(v.y - __bfloat162float(hy));
    __nv_bfloat16 lz = __float2bfloat16(v.z - __bfloat162float(hz));
    __nv_bfloat16 lw = __float2bfloat16(v.w - __bfloat162float(hw));
    __nv_bfloat162 l01 = __halves2bfloat162(lx, ly), l23 = __halves2bfloat162(lz, lw);
    hi = make_uint2(*(uint32_t*)&h01, *(uint32_t*)&h23);
    lo = make_uint2(*(uint32_t*)&l01, *(uint32_t*)&l23);
}
__device__ __forceinline__ void split2(float a, float b, uint32_t& hi, uint32_t& lo) {
    __nv_bfloat16 ha = __float2bfloat16(a), hb = __float2bfloat16(b);
    __nv_bfloat16 la = __float2bfloat16(a - __bfloat162float(ha));
    __nv_bfloat16 lb = __float2bfloat16(b - __bfloat162float(hb));
    __nv_bfloat162 hp = __halves2bfloat162(ha, hb), lp = __halves2bfloat162(la, lb);
    hi = *(uint32_t*)&hp; lo = *(uint32_t*)&lp;
}
__device__ __forceinline__ void split1(float v, __nv_bfloat16& h, __nv_bfloat16& l) {
    h = __float2bfloat16(v);
    l = __float2bfloat16(v - __bfloat162float(h));
}

// gemm stage store — 512-thread version (2 iterations)
__device__ __forceinline__ void store_stage(char* sb, int t, const float4* pa, const float4* pb) {
    #pragma unroll
    for (int i = 0; i < 2; ++i) {
        int idx = t + i * 512, row = idx >> 3, c4 = idx & 7;
        uint32_t off = (uint32_t)(row * TSTR + c4 * 8);
        uint2 hi, lo;
        split4(pa[i], hi, lo);
        *(uint2*)(sb + OFF_AHI + off) = hi;
        *(uint2*)(sb + OFF_ALO + off) = lo;
        split4(pb[i], hi, lo);
        *(uint2*)(sb + OFF_BHI + off) = hi;
        *(uint2*)(sb + OFF_BLO + off) = lo;
    }
}

// ---------------------------------------------------------------------------
// GEMM mainloop — 512 threads, 16 warps (4M x 4N), warp tile 32x32. (R8)
// ---------------------------------------------------------------------------
__device__ __forceinline__ void mma_mainloop(
    const float* __restrict__ A, int lda,
    const float* __restrict__ B, int ldb, int K,
    float c[2][4][4])
{
    extern __shared__ __align__(16) char smem[];
    const int t    = threadIdx.x;
    const int lane = t & 31;
    const int warp = t >> 5;
    const int wm   = warp >> 2;
    const int wn   = warp & 3;
    const uint32_t sm = smem_u32(smem);

    const uint32_t a_off = (uint32_t)((wm * 32 + (lane & 15)) * TSTR + (lane >> 4) * 16);
    const uint32_t b_off = (uint32_t)(OFF_BHI + (wn * 32 + ((lane >> 4) * 8) + (lane & 7)) * TSTR + ((lane >> 3) & 1) * 16);

    float4 pa[2], pb[2];
    const int nch = K / BK;

    #pragma unroll
    for (int i = 0; i < 2; ++i) {
        int idx = t + i * 512, row = idx >> 3, c4 = idx & 7;
        pa[i] = *(const float4*)(A + (size_t)row * lda + c4 * 4);
        pb[i] = *(const float4*)(B + (size_t)row * ldb + c4 * 4);
    }
    store_stage(smem, t, pa, pb);
    __syncthreads();

    uint32_t buf = 0;
    for (int ch = 0; ch < nch; ++ch) {
        if (ch + 1 < nch) {
            const int k0 = (ch + 1) * BK;
            #pragma unroll
            for (int i = 0; i < 2; ++i) {
                int idx = t + i * 512, row = idx >> 3, c4 = idx & 7;
                pa[i] = *(const float4*)(A + (size_t)row * lda + k0 + c4 * 4);
                pb[i] = *(const float4*)(B + (size_t)row * ldb + k0 + c4 * 4);
            }
        }
        const uint32_t sb = sm + buf * STAGE_B;
        #pragma unroll
        for (int ks = 0; ks < 2; ++ks) {
            uint32_t ah[2][4], al[2][4], bh[4][2], bl[4][2];
            #pragma unroll
            for (int mt = 0; mt < 2; ++mt) {
                uint32_t ad = sb + a_off + (uint32_t)(mt * 16 * TSTR + ks * 32);
                ldmx4(ah[mt][0], ah[mt][1], ah[mt][2], ah[mt][3], ad + OFF_AHI);
                ldmx4(al[mt][0], al[mt][1], al[mt][2], al[mt][3], ad + OFF_ALO);
            }
            #pragma unroll
            for (int np = 0; np < 2; ++np) {
                uint32_t ad = sb + b_off + (uint32_t)(np * 16 * TSTR + ks * 32);
                ldmx4(bh[np * 2][0], bh[np * 2][1], bh[np * 2 + 1][0], bh[np * 2 + 1][1], ad);
                ldmx4(bl[np * 2][0], bl[np * 2][1], bl[np * 2 + 1][0], bl[np * 2 + 1][1], ad + TILE_B);
            }
            #pragma unroll
            for (int mt = 0; mt < 2; ++mt)
                #pragma unroll
                for (int nt = 0; nt < 4; ++nt) {
                    mma16816(c[mt][nt], ah[mt], bh[nt]);
                    mma16816(c[mt][nt], ah[mt], bl[nt]);
                    mma16816(c[mt][nt], al[mt], bh[nt]);
                }
        }
        if (ch + 1 < nch)
            store_stage(smem + (buf ^ 1) * STAGE_B, t, pa, pb);
        __syncthreads();
        buf ^= 1;
    }
}

#define ACC_INIT4(c) \
    _Pragma("unroll") for (int mt = 0; mt < 2; ++mt) \
    _Pragma("unroll") for (int nt = 0; nt < 4; ++nt) \
    _Pragma("unroll") for (int i = 0; i < 4; ++i) c[mt][nt][i] = 0.f

// ---------------------------------------------------------------------------
// Generic NT GEMM (unchanged from R8)
// ---------------------------------------------------------------------------
__global__ __launch_bounds__(512) void gemm_nt_mma(
    const float* __restrict__ A, int lda,
    const float* __restrict__ B, int ldb,
    float* __restrict__ C, int ldc, int K,
    const float* __restrict__ bias)
{
    const int m0 = blockIdx.y * 128, n0 = blockIdx.x * 128;
    float c[2][4][4];
    ACC_INIT4(c);

    mma_mainloop(A + (size_t)m0 * lda, lda, B + (size_t)n0 * ldb, ldb, K, c);

    const int lane = threadIdx.x & 31, warp = threadIdx.x >> 5;
    const int rb = m0 + (warp >> 2) * 32 + (lane >> 2);
    const int cb = n0 + (warp & 3) * 32 + (lane & 3) * 2;
    #pragma unroll
    for (int mt = 0; mt < 2; ++mt)
        #pragma unroll
        for (int nt = 0; nt < 4; ++nt) {
            int row = rb + mt * 16, col = cb + nt * 8;
            float b0 = bias ? bias[col] : 0.f, b1 = bias ? bias[col + 1] : 0.f;
            *(float2*)(C + (size_t)row * ldc + col)       = make_float2(c[mt][nt][0] + b0, c[mt][nt][1] + b1);
            *(float2*)(C + (size_t)(row + 8) * ldc + col) = make_float2(c[mt][nt][2] + b0, c[mt][nt][3] + b1);
        }
}

// ---------------------------------------------------------------------------
// Fused flash attention — operands PRE-SPLIT bf16 hi/lo in global.
// Loader is pure uint4 LDG -> STS (no conversion).
// ---------------------------------------------------------------------------
__global__ __launch_bounds__(256) void flash_attn(const float* __restrict__ mask)
{
    extern __shared__ __align__(16) char smem[];
    const int z = blockIdx.z, b = z / HH, h = z % HH, hkv = h % HKV;
    const int m0 = blockIdx.y * 128;
    const int t = threadIdx.x, lane = t & 31, w = t >> 5;
    const uint32_t sm = smem_u32(smem);

    // ---- load Q tile [128 x HD] bf16 hi/lo (once) ----
    {
        const __nv_bfloat16* Qh = g_Qh + ((size_t)(b * NN + m0) * HH + h) * HD;
        const __nv_bfloat16* Ql = g_Ql + ((size_t)(b * NN + m0) * HH + h) * HD;
        #pragma unroll
        for (int i = 0; i < 8; ++i) {
            int idx = t + i * 256, row = idx >> 4, c16 = idx & 15;
            uint32_t off = (uint32_t)(row * KSTR + c16 * 16);
            size_t g = (size_t)row * (HH * HD) + c16 * 8;
            *(uint4*)(smem + F_QHI + off) = *(const uint4*)(Qh + g);
            *(uint4*)(smem + F_QLO + off) = *(const uint4*)(Ql + g);
        }
    }

    float co[16][4];
    #pragma unroll
    for (int nt = 0; nt < 16; ++nt)
        #pragma unroll
        for (int i = 0; i < 4; ++i) co[nt][i] = 0.f;
    float m0r = -INFINITY, m1r = -INFINITY;
    float l0r = 0.f, l1r = 0.f;

    const uint32_t qa_off = (uint32_t)((w * 16 + (lane & 15)) * KSTR + (lane >> 4) * 16);
    const uint32_t kb_base = (uint32_t)(((lane >> 4) * 8 + (lane & 7)) * KSTR + ((lane >> 3) & 1) * 16);
    const uint32_t pa_off = (uint32_t)((w * 16 + (lane & 15)) * VSTR + (lane >> 4) * 16);
    const uint32_t vb_base = (uint32_t)(((lane >> 4) * 8 + (lane & 7)) * VSTR + ((lane >> 3) & 1) * 16);

    __syncthreads();

    for (int ch = 0; ch < NN / 64; ++ch) {
        const int n0 = ch * 64;
        // ---- load K chunk [64 x HD] bf16 hi/lo ----
        {
            const __nv_bfloat16* Kh = g_Kh + ((size_t)(b * NN + n0) * HKV + hkv) * HD;
            const __nv_bfloat16* Kl = g_Kl + ((size_t)(b * NN + n0) * HKV + hkv) * HD;
            #pragma unroll
            for (int i = 0; i < 4; ++i) {
                int idx = t + i * 256, row = idx >> 4, c16 = idx & 15;
                uint32_t off = (uint32_t)(row * KSTR + c16 * 16);
                size_t g = (size_t)row * (HKV * HD) + c16 * 8;
                *(uint4*)(smem + F_KHI + off) = *(const uint4*)(Kh + g);
                *(uint4*)(smem + F_KLO + off) = *(const uint4*)(Kl + g);
            }
        }
        // ---- load V chunk [128(hd) x 64(n)] bf16 hi/lo ----
        {
            const __nv_bfloat16* Vh = g_Vth + (size_t)(b * HKV + hkv) * HD * NN + n0;
            const __nv_bfloat16* Vl = g_Vtl + (size_t)(b * HKV + hkv) * HD * NN + n0;
            #pragma unroll
            for (int i = 0; i < 4; ++i) {
                int idx = t + i * 256, row = idx >> 3, c16 = idx & 7;
                uint32_t off = (uint32_t)(row * VSTR + c16 * 16);
                size_t g = (size_t)row * NN + c16 * 8;
                *(uint4*)(smem + F_VHI + off) = *(const uint4*)(Vh + g);
                *(uint4*)(smem + F_VLO + off) = *(const uint4*)(Vl + g);
            }
        }
        __syncthreads();

        // ---- S = Q @ Kc^T : warp computes 16 x 64 ----
        float cs[8][4];
        #pragma unroll
        for (int nt = 0; nt < 8; ++nt)
            #pragma unroll
            for (int i = 0; i < 4; ++i) cs[nt][i] = 0.f;

        #pragma unroll
        for (int ks = 0; ks < 8; ++ks) {
            uint32_t ah[4], al[4];
            uint32_t ad = sm + qa_off + (uint32_t)(ks * 32);
            ldmx4(ah[0], ah[1], ah[2], ah[3], ad + F_QHI);
            ldmx4(al[0], al[1], al[2], al[3], ad + F_QLO);
            #pragma unroll
            for (int np = 0; np < 4; ++np) {
                uint32_t bd = sm + kb_base + (uint32_t)(np * 16 * KSTR + ks * 32);
                uint32_t bh[2][2], bl[2][2];
                ldmx4(bh[0][0], bh[0][1], bh[1][0], bh[1][1], bd + F_KHI);
                ldmx4(bl[0][0], bl[0][1], bl[1][0], bl[1][1], bd + F_KLO);
                #pragma unroll
                for (int q = 0; q < 2; ++q) {
                    mma16816(cs[np * 2 + q], ah, bh[q]);
                    mma16816(cs[np * 2 + q], ah, bl[q]);
                    mma16816(cs[np * 2 + q], al, bh[q]);
                }
            }
        }

        // ---- scale + mask bias ----
        #pragma unroll
        for (int nt = 0; nt < 8; ++nt) {
            int col = n0 + nt * 8 + (lane & 3) * 2;
            float mb0 = (1.0f - mask[b * NN + col]) * -1e9f;
            float mb1 = (1.0f - mask[b * NN + col + 1]) * -1e9f;
            cs[nt][0] = cs[nt][0] * SCALE + mb0;
            cs[nt][1] = cs[nt][1] * SCALE + mb1;
            cs[nt][2] = cs[nt][2] * SCALE + mb0;
            cs[nt][3] = cs[nt][3] * SCALE + mb1;
        }

        // ---- online softmax ----
        float cm0 = -INFINITY, cm1 = -INFINITY;
        #pragma unroll
        for (int nt = 0; nt < 8; ++nt) {
            cm0 = fmaxf(cm0, fmaxf(cs[nt][0], cs[nt][1]));
            cm1 = fmaxf(cm1, fmaxf(cs[nt][2], cs[nt][3]));
        }
        cm0 = fmaxf(cm0, __shfl_xor_sync(0xFFFFFFFF, cm0, 1));
        cm0 = fmaxf(cm0, __shfl_xor_sync(0xFFFFFFFF, cm0, 2));
        cm1 = fmaxf(cm1, __shfl_xor_sync(0xFFFFFFFF, cm1, 1));
        cm1 = fmaxf(cm1, __shfl_xor_sync(0xFFFFFFFF, cm1, 2));

        float mn0 = fmaxf(m0r, cm0), mn1 = fmaxf(m1r, cm1);
        float f0 = __expf(m0r - mn0), f1 = __expf(m1r - mn1);
        m0r = mn0; m1r = mn1;

        float rs0 = 0.f, rs1 = 0.f;
        #pragma unroll
        for (int nt = 0; nt < 8; ++nt) {
            cs[nt][0] = __expf(cs[nt][0] - mn0);
            cs[nt][1] = __expf(cs[nt][1] - mn0);
            cs[nt][2] = __expf(cs[nt][2] - mn1);
            cs[nt][3] = __expf(cs[nt][3] - mn1);
            rs0 += cs[nt][0] + cs[nt][1];
            rs1 += cs[nt][2] + cs[nt][3];
        }
        rs0 += __shfl_xor_sync(0xFFFFFFFF, rs0, 1);
        rs0 += __shfl_xor_sync(0xFFFFFFFF, rs0, 2);
        rs1 += __shfl_xor_sync(0xFFFFFFFF, rs1, 1);
        rs1 += __shfl_xor_sync(0xFFFFFFFF, rs1, 2);
        l0r = l0r * f0 + rs0;
        l1r = l1r * f1 + rs1;

        #pragma unroll
        for (int nt = 0; nt < 16; ++nt) {
            co[nt][0] *= f0; co[nt][1] *= f0;
            co[nt][2] *= f1; co[nt][3] *= f1;
        }

        // ---- store P hi/lo to smem ----
        {
            int r0 = lane >> 2;
            uint32_t base0 = (uint32_t)((w * 16 + r0) * VSTR + (lane & 3) * 4);
            #pragma unroll
            for (int nt = 0; nt < 8; ++nt) {
                uint32_t hi, lo;
                split2(cs[nt][0], cs[nt][1], hi, lo);
                uint32_t o0 = base0 + nt * 16;
                *(uint32_t*)(smem + F_PHI + o0) = hi;
                *(uint32_t*)(smem + F_PLO + o0) = lo;
                split2(cs[nt][2], cs[nt][3], hi, lo);
                uint32_t o1 = o0 + 8 * VSTR;
                *(uint32_t*)(smem + F_PHI + o1) = hi;
                *(uint32_t*)(smem + F_PLO + o1) = lo;
            }
        }
        __syncthreads();

        // ---- O += P @ Vc ----
        #pragma unroll
        for (int ks = 0; ks < 4; ++ks) {
            uint32_t ah[4], al[4];
            uint32_t ad = sm + pa_off + (uint32_t)(ks * 32);
            ldmx4(ah[0], ah[1], ah[2], ah[3], ad + F_PHI);
            ldmx4(al[0], al[1], al[2], al[3], ad + F_PLO);
            #pragma unroll
            for (int np = 0; np < 8; ++np) {
                uint32_t bd = sm + vb_base + (uint32_t)(np * 16 * VSTR + ks * 32);
                uint32_t bh[2][2], bl[2][2];
                ldmx4(bh[0][0], bh[0][1], bh[1][0], bh[1][1], bd + F_VHI);
                ldmx4(bl[0][0], bl[0][1], bl[1][0], bl[1][1], bd + F_VLO);
                #pragma unroll
                for (int q = 0; q < 2; ++q) {
                    mma16816(co[np * 2 + q], ah, bh[q]);
                    mma16816(co[np * 2 + q], ah, bl[q]);
                    mma16816(co[np * 2 + q], al, bh[q]);
                }
            }
        }
        __syncthreads();
    }

    float inv0 = 1.0f / l0r, inv1 = 1.0f / l1r;
    int r0 = lane >> 2;
    #pragma unroll
    for (int nt = 0; nt < 16; ++nt) {
        int row = m0 + w * 16 + r0;
        int col = nt * 8 + (lane & 3) * 2;
        float* p0 = g_ctx + (size_t)(b * NN + row) * (HH * HD) + h * HD + col;
        float* p1 = g_ctx + (size_t)(b * NN + row + 8) * (HH * HD) + h * HD + col;
        *(float2*)p0 = make_float2(co[nt][0] * inv0, co[nt][1] * inv0);
        *(float2*)p1 = make_float2(co[nt][2] * inv1, co[nt][3] * inv1);
    }
}

// ---------------------------------------------------------------------------
// Transposes (weights, fp32 — unchanged)
// ---------------------------------------------------------------------------
__global__ void transpose_f32(const float* __restrict__ src, float* __restrict__ dst,
                              int R, int C)
{
    __shared__ float tile[32][33];
    int c0 = blockIdx.x * 32, r0 = blockIdx.y * 32;
    int tx = threadIdx.x, ty = threadIdx.y;
    #pragma unroll
    for (int i = ty; i < 32; i += 8)
        tile[i][tx] = src[(size_t)(r0 + i) * C + c0 + tx];
    __syncthreads();
    #pragma unroll
    for (int i = ty; i < 32; i += 8)
        dst[(size_t)(c0 + i) * R + r0 + tx] = tile[tx][i];
}

// V: [b][n][hkv][hd] (inside g_QKV, fp32) -> Vt [b][hkv][hd][n] bf16 hi/lo
__global__ void transpose_v_split()
{
    __shared__ float tile[32][33];
    int z = blockIdx.z, b = z / HKV, hkv = z % HKV;
    int n0 = blockIdx.x * 32, d0 = blockIdx.y * 32;
    int tx = threadIdx.x, ty = threadIdx.y;
    #pragma unroll
    for (int i = ty; i < 32; i += 8)
        tile[i][tx] = g_QKV[(size_t)(b * NN + n0 + i) * QKVW + VOFF + hkv * HD + d0 + tx];
    __syncthreads();
    size_t base = (size_t)(b * HKV + hkv) * HD * NN;
    #pragma unroll
    for (int i = ty; i < 32; i += 8) {
        float v = tile[tx][i];
        __nv_bfloat16 h, l;
        split1(v, h, l);
        size_t off = base + (size_t)(d0 + i) * NN + n0 + tx;
        g_Vth[off] = h; g_Vtl[off] = l;
    }
}

// ---------------------------------------------------------------------------
// RoPE + split: g_QKV(fp32) -> Qh/Ql [b][n][h][hd], Kh/Kl [b][n][hkv][hd]
// ---------------------------------------------------------------------------
__global__ void rope_split(const float* __restrict__ cosb,
                           const float* __restrict__ sinb)
{
    int idx = blockIdx.x * blockDim.x + threadIdx.x;
    const int NQ = BB * NN * HH * (HD / 2);
    const int NK = BB * NN * HKV * (HD / 2);
    if (idx < NQ) {
        int i  = idx & 63;
        int h  = (idx >> 6) % HH;
        int bn = idx / (64 * HH);
        int n  = bn % NN;
        float cc = cosb[n * 64 + i], ss = sinb[n * 64 + i];
        const float* q = g_QKV + (size_t)bn * QKVW + h * HD;
        float t1 = q[i], t2 = q[i + 64];
        float r1 = t1 * cc + t2 * ss;
        float r2 = t2 * cc - t1 * ss;
        size_t o = ((size_t)bn * HH + h) * HD;
        __nv_bfloat16 h1, l1, h2, l2;
        split1(r1, h1, l1); split1(r2, h2, l2);
        g_Qh[o + i] = h1; g_Ql[o + i] = l1;
        g_Qh[o + i + 64] = h2; g_Ql[o + i + 64] = l2;
    } else {
        idx -= NQ;
        if (idx < NK) {
            int i  = idx & 63;
            int hk = (idx >> 6) % HKV;
            int bn = idx / (64 * HKV);
            int n  = bn % NN;
            float cc = cosb[n * 64 + i], ss = sinb[n * 64 + i];
            const float* k = g_QKV + (size_t)bn * QKVW + KOFF + hk * HD;
            float t1 = k[i], t2 = k[i + 64];
            float r1 = t1 * cc + t2 * ss;
            float r2 = t2 * cc - t1 * ss;
            size_t o = ((size_t)bn * HKV + hk) * HD;
            __nv_bfloat16 h1, l1, h2, l2;
            split1(r1, h1, l1); split1(r2, h2, l2);
            g_Kh[o + i] = h1; g_Kl[o + i] = l1;
            g_Kh[o + i + 64] = h2; g_Kl[o + i + 64] = l2;
        }
    }
}

// ---------------------------------------------------------------------------
// Launch
// ---------------------------------------------------------------------------
extern "C" void kernel_launch(void* const* d_in, const int* in_sizes, int n_in,
                              void* d_out, int out_size)
{
    (void)in_sizes; (void)n_in; (void)out_size;

    const float* x    = (const float*)d_in[0];
    const float* cosb = (const float*)d_in[1];
    const float* sinb = (const float*)d_in[2];
    const float* mask = (const float*)d_in[3];
    const float* Wq   = (const float*)d_in[4];
    const float* Wkv  = (const float*)d_in[5];
    const float* Wo   = (const float*)d_in[6];
    const float* bo   = (const float*)d_in[7];
    float* out = (float*)d_out;

    float *pQKV, *pWT, *pWoT, *pCtx;
    cudaGetSymbolAddress((void**)&pQKV, g_QKV);
    cudaGetSymbolAddress((void**)&pWT,  g_WT);
    cudaGetSymbolAddress((void**)&pWoT, g_WoT);
    cudaGetSymbolAddress((void**)&pCtx, g_ctx);

    cudaFuncSetAttribute(gemm_nt_mma, cudaFuncAttributeMaxDynamicSharedMemorySize, SMEM_SZ);
    cudaFuncSetAttribute(flash_attn,  cudaFuncAttributeMaxDynamicSharedMemorySize, F_SZ);

    const int M = BB * NN;   // 4096
    dim3 tb(32, 8);

    // Weight transposes
    transpose_f32<<<dim3(DD / 32, DD / 32), tb>>>(Wq, pWT, DD, DD);
    transpose_f32<<<dim3((2 * HKV * HD) / 32, DD / 32), tb>>>(Wkv, pWT + (size_t)KOFF * DD, DD, 2 * HKV * HD);
    transpose_f32<<<dim3(DD / 32, DD / 32), tb>>>(Wo, pWoT, DD, DD);

    // QKV = x @ [Wq|Wkv]
    gemm_nt_mma<<<dim3(QKVW / 128, M / 128), 512, SMEM_SZ>>>(x, DD, pWT, DD, pQKV, QKVW, DD, nullptr);

    // RoPE + split -> bf16 hi/lo Q, K
    {
        int total = BB * NN * HH * (HD / 2) + BB * NN * HKV * (HD / 2);
        rope_split<<<(total + 255) / 256, 256>>>(cosb, sinb);
    }

    // V transpose + split -> bf16 hi/lo Vt
    transpose_v_split<<<dim3(NN / 32, HD / 32, BB * HKV), tb>>>();

    // fused attention
    flash_attn<<<dim3(1, NN / 128, BB * HH), 256, F_SZ>>>(mask);

    // out = ctx @ Wo + bo
    gemm_nt_mma<<<dim3(DD / 128, M / 128), 512, SMEM_SZ>>>(pCtx, HH * HD, pWoT, DD, out, DD, DD, bo);
}